// round 11
// baseline (speedup 1.0000x reference)
#include <cuda_runtime.h>
#include <cuda_bf16.h>
#include <cmath>
#include <cstdint>

// ---------------- problem constants ----------------
#define B_   8
#define S_   1024
#define D_   1024
#define NH_  16
#define HD_  64
#define M_   (B_ * S_)          // 8192 rows
#define DFF_ (4 * D_)           // 4096
#define LN_EPS 1e-5f
#define LORA_SCALE 0.25f

// ---------------- scratch (device globals) -----------
__device__ float g_qf [M_ * D_];
__device__ float g_kf [M_ * D_];
__device__ float g_vf [M_ * D_];
__device__ float g_x1 [M_ * D_];
__device__ float g_tk [M_ * 4];
__device__ float g_tv [M_ * 4];
__device__ float g_to [M_ * 4];
__device__ __nv_bfloat16 g_ah[M_ * D_];      // activation hi
__device__ __nv_bfloat16 g_al[M_ * D_];      // activation lo
__device__ __nv_bfloat16 g_uh[M_ * DFF_];    // MLP hidden hi
__device__ __nv_bfloat16 g_ul[M_ * DFF_];    // MLP hidden lo
__device__ __nv_bfloat16 g_wh[12 * 1024 * 1024];  // weights hi
__device__ __nv_bfloat16 g_wl[12 * 1024 * 1024];  // weights lo

// ================= helpers =================
__device__ __forceinline__ uint32_t smem_to_u32(const void* p) {
    uint32_t a;
    asm("{ .reg .u64 t; cvta.to.shared.u64 t, %1; cvt.u32.u64 %0, t; }" : "=r"(a) : "l"(p));
    return a;
}
__device__ __forceinline__ void cp_async16(uint32_t dst, const void* src) {
    asm volatile("cp.async.cg.shared.global [%0], [%1], 16;" :: "r"(dst), "l"(src));
}
#define CP_COMMIT()  asm volatile("cp.async.commit_group;" ::: "memory")
#define CP_WAIT0()   asm volatile("cp.async.wait_group 0;" ::: "memory")

#define LDSM4(r, addr)                                                         \
    asm volatile("ldmatrix.sync.aligned.m8n8.x4.shared.b16 {%0,%1,%2,%3}, [%4];" \
        : "=r"((r)[0]), "=r"((r)[1]), "=r"((r)[2]), "=r"((r)[3]) : "r"(addr))

#define MMA_BF16(d, a, b)                                                      \
    asm volatile(                                                              \
        "mma.sync.aligned.m16n8k16.row.col.f32.bf16.bf16.f32 "                 \
        "{%0,%1,%2,%3}, {%4,%5,%6,%7}, {%8,%9}, {%0,%1,%2,%3};"                \
        : "+f"((d)[0]), "+f"((d)[1]), "+f"((d)[2]), "+f"((d)[3])               \
        : "r"((a)[0]), "r"((a)[1]), "r"((a)[2]), "r"((a)[3]),                  \
          "r"((b)[0]), "r"((b)[1]))

// ================= mma.sync GEMM (3-pass bf16 split) =================
// BM=BN=128, BK=32, 256 threads (8 warps 2x4), warp tile 64x32.
// THIS ROUND: ldmatrix.x4 fragment loads + single barrier per chunk.
// EPI: 0 = fp32 +bias | 1 = gelu->bf16 split | 2 = +bias? +rank4 |
//      3 = resid + bias + rank4 | 4 = resid + bias
#define SROW 40                       // halves per smem row (80B)
#define TILE_B (128 * SROW * 2)       // 10240 bytes
#define STAGE_B (4 * TILE_B)
#define GEMM_SMEM (2 * STAGE_B)       // 81920

template<int EPI>
__global__ void __launch_bounds__(256)
gemm_tc(const __nv_bfloat16* __restrict__ Ah, const __nv_bfloat16* __restrict__ Al,
        const __nv_bfloat16* __restrict__ Bh, const __nv_bfloat16* __restrict__ Bl,
        const float* __restrict__ bias, float* __restrict__ C,
        __nv_bfloat16* __restrict__ Ch, __nv_bfloat16* __restrict__ Cl,
        const float* __restrict__ resid, const float* __restrict__ t4,
        const float* __restrict__ lb,
        int M, int N, int K)
{
    extern __shared__ char sm[];
    const uint32_t smem_u32 = smem_to_u32(sm);
    const int tid  = threadIdx.x;
    const int lane = tid & 31;
    const int g    = lane >> 2, tg = lane & 3;
    const int w    = tid >> 5;
    const int wm   = w >> 2;          // 0..1
    const int wn   = w & 3;           // 0..3
    const int bm   = blockIdx.y * 128, bn = blockIdx.x * 128;

    const size_t rowb = (size_t)K * 2;
    const char* srcA_h = (const char*)(Ah + (size_t)bm * K);
    const char* srcA_l = (const char*)(Al + (size_t)bm * K);
    const char* srcB_h = (const char*)(Bh + (size_t)bn * K);
    const char* srcB_l = (const char*)(Bl + (size_t)bn * K);

    const int NC = K >> 5;

    // per-lane ldmatrix base offsets (bytes)
    // A (m16k16 frag): lanes 0-15 -> rows m0..15 @k0; lanes 16-31 -> same rows @k+8
    const uint32_t a_lane = (uint32_t)(((wm * 64 + (lane & 15)) * SROW + 8 * (lane >> 4)) * 2);
    // B (k16n8 frags, 2 n-tiles): lanes map n rows with (lane>>3)&1 selecting k half
    const uint32_t b_lane = (uint32_t)(((wn * 32 + (lane & 7) + (lane >> 4) * 8) * SROW
                                       + ((lane >> 3) & 1) * 8) * 2);

    auto load_chunk = [&](int c, int s) {
        const uint32_t sb = smem_u32 + s * STAGE_B;
        const size_t coff = (size_t)c * 64;
        #pragma unroll
        for (int t = 0; t < 2; t++) {
            const int unit = tid + t * 256;
            const int row = unit >> 2, cb = unit & 3;
            const size_t so = (size_t)row * rowb + coff + cb * 16;
            const uint32_t doff = row * 80 + cb * 16;
            cp_async16(sb + 0 * TILE_B + doff, srcA_h + so);
            cp_async16(sb + 1 * TILE_B + doff, srcA_l + so);
            cp_async16(sb + 2 * TILE_B + doff, srcB_h + so);
            cp_async16(sb + 3 * TILE_B + doff, srcB_l + so);
        }
        CP_COMMIT();
    };

    float acc[4][4][4];
    #pragma unroll
    for (int mi = 0; mi < 4; mi++)
        #pragma unroll
        for (int ni = 0; ni < 4; ni++)
            #pragma unroll
            for (int q = 0; q < 4; q++) acc[mi][ni][q] = 0.f;

    load_chunk(0, 0);

    for (int c = 0; c < NC; c++) {
        const int s = c & 1;
        CP_WAIT0();
        __syncthreads();
        if (c + 1 < NC) load_chunk(c + 1, s ^ 1);

        const uint32_t st = smem_u32 + s * STAGE_B;
        const uint32_t ah_b = st + 0 * TILE_B + a_lane;
        const uint32_t al_b = st + 1 * TILE_B + a_lane;
        const uint32_t bh_b = st + 2 * TILE_B + b_lane;
        const uint32_t bl_b = st + 3 * TILE_B + b_lane;

        #pragma unroll
        for (int ks = 0; ks < 2; ks++) {
            const uint32_t kso = ks * 32;     // 16 halves
            uint32_t bh[2][4], bl[2][4];
            #pragma unroll
            for (int p = 0; p < 2; p++) {
                LDSM4(bh[p], bh_b + p * (16 * SROW * 2) + kso);
                LDSM4(bl[p], bl_b + p * (16 * SROW * 2) + kso);
            }
            #pragma unroll
            for (int mi = 0; mi < 4; mi++) {
                uint32_t ah[4], al[4];
                LDSM4(ah, ah_b + mi * (16 * SROW * 2) + kso);
                LDSM4(al, al_b + mi * (16 * SROW * 2) + kso);
                #pragma unroll
                for (int ni = 0; ni < 4; ni++) {
                    uint32_t* pbh = &bh[ni >> 1][(ni & 1) * 2];
                    uint32_t* pbl = &bl[ni >> 1][(ni & 1) * 2];
                    MMA_BF16(acc[mi][ni], ah, pbh);
                    MMA_BF16(acc[mi][ni], ah, pbl);
                    MMA_BF16(acc[mi][ni], al, pbh);
                }
            }
        }
    }

    // ---- fused epilogue (identical to measured R10) ----
    #pragma unroll
    for (int mi = 0; mi < 4; mi++) {
        const int row0 = bm + wm * 64 + mi * 16 + g;
        float4 tr0, tr1;
        if (EPI == 2 || EPI == 3) {
            tr0 = *(const float4*)(t4 + (size_t)row0 * 4);
            tr1 = *(const float4*)(t4 + (size_t)(row0 + 8) * 4);
        }
        #pragma unroll
        for (int ni = 0; ni < 4; ni++) {
            const int col = bn + wn * 32 + ni * 8 + 2 * tg;
            const float bx = bias ? bias[col]     : 0.f;
            const float by = bias ? bias[col + 1] : 0.f;
            float v0 = acc[mi][ni][0] + bx, v1 = acc[mi][ni][1] + by;
            float v2 = acc[mi][ni][2] + bx, v3 = acc[mi][ni][3] + by;
            if (EPI == 2 || EPI == 3) {
                float4 c0 = *(const float4*)(lb + (size_t)col * 4);
                float4 c1 = *(const float4*)(lb + (size_t)(col + 1) * 4);
                v0 += LORA_SCALE * (tr0.x*c0.x + tr0.y*c0.y + tr0.z*c0.z + tr0.w*c0.w);
                v1 += LORA_SCALE * (tr0.x*c1.x + tr0.y*c1.y + tr0.z*c1.z + tr0.w*c1.w);
                v2 += LORA_SCALE * (tr1.x*c0.x + tr1.y*c0.y + tr1.z*c0.z + tr1.w*c0.w);
                v3 += LORA_SCALE * (tr1.x*c1.x + tr1.y*c1.y + tr1.z*c1.z + tr1.w*c1.w);
            }
            if (EPI == 3 || EPI == 4) {
                v0 += resid[(size_t)row0 * N + col];
                v1 += resid[(size_t)row0 * N + col + 1];
                v2 += resid[(size_t)(row0 + 8) * N + col];
                v3 += resid[(size_t)(row0 + 8) * N + col + 1];
            }
            if (EPI == 1) {
                v0 = 0.5f * v0 * (1.0f + erff(v0 * 0.70710678118654752f));
                v1 = 0.5f * v1 * (1.0f + erff(v1 * 0.70710678118654752f));
                v2 = 0.5f * v2 * (1.0f + erff(v2 * 0.70710678118654752f));
                v3 = 0.5f * v3 * (1.0f + erff(v3 * 0.70710678118654752f));
                __nv_bfloat16 h0 = __float2bfloat16(v0), h1 = __float2bfloat16(v1);
                __nv_bfloat16 h2 = __float2bfloat16(v2), h3 = __float2bfloat16(v3);
                __nv_bfloat162 hp0 = {h0, h1}, hp1 = {h2, h3};
                __nv_bfloat162 lp0 = {__float2bfloat16(v0 - __bfloat162float(h0)),
                                      __float2bfloat16(v1 - __bfloat162float(h1))};
                __nv_bfloat162 lp1 = {__float2bfloat16(v2 - __bfloat162float(h2)),
                                      __float2bfloat16(v3 - __bfloat162float(h3))};
                *(uint32_t*)(Ch + (size_t)row0 * N + col)       = *(uint32_t*)&hp0;
                *(uint32_t*)(Ch + (size_t)(row0 + 8) * N + col) = *(uint32_t*)&hp1;
                *(uint32_t*)(Cl + (size_t)row0 * N + col)       = *(uint32_t*)&lp0;
                *(uint32_t*)(Cl + (size_t)(row0 + 8) * N + col) = *(uint32_t*)&lp1;
            } else {
                *(float2*)(C + (size_t)row0 * N + col)       = make_float2(v0, v1);
                *(float2*)(C + (size_t)(row0 + 8) * N + col) = make_float2(v2, v3);
            }
        }
    }
}

// ---------------- weight fp32 -> bf16 hi/lo split ----------------
__global__ void split_kernel(const float* __restrict__ in,
                             __nv_bfloat16* __restrict__ hi,
                             __nv_bfloat16* __restrict__ lo, int n4)
{
    int i = blockIdx.x * blockDim.x + threadIdx.x;
    if (i >= n4) return;
    float4 v = ((const float4*)in)[i];
    __align__(8) __nv_bfloat16 h[4], l[4];
    #pragma unroll
    for (int j = 0; j < 4; j++) {
        float x = (&v.x)[j];
        __nv_bfloat16 hh = __float2bfloat16(x);
        h[j] = hh;
        l[j] = __float2bfloat16(x - __bfloat162float(hh));
    }
    ((uint2*)hi)[i] = *(const uint2*)h;
    ((uint2*)lo)[i] = *(const uint2*)l;
}

// ---------------- fused LayerNorm + bf16 split ----------------
__global__ void ln_split_kernel(const float* __restrict__ x,
                                const float* __restrict__ g,
                                const float* __restrict__ b,
                                __nv_bfloat16* __restrict__ hi,
                                __nv_bfloat16* __restrict__ lo)
{
    __shared__ float red[16];
    const int row = blockIdx.x;
    const int i0 = threadIdx.x * 4;
    const float* xr = x + (size_t)row * D_;
    float4 v = *(const float4*)(xr + i0);
    float s  = v.x + v.y + v.z + v.w;
    float sq = v.x*v.x + v.y*v.y + v.z*v.z + v.w*v.w;
    #pragma unroll
    for (int o = 16; o >= 1; o >>= 1) {
        s  += __shfl_xor_sync(0xffffffffu, s,  o);
        sq += __shfl_xor_sync(0xffffffffu, sq, o);
    }
    int w = threadIdx.x >> 5, lane = threadIdx.x & 31;
    if (lane == 0) { red[w] = s; red[w + 8] = sq; }
    __syncthreads();
    if (threadIdx.x == 0) {
        float ts = 0.f, tq = 0.f;
        #pragma unroll
        for (int i = 0; i < 8; i++) { ts += red[i]; tq += red[i + 8]; }
        float mean = ts * (1.0f / D_);
        float var  = tq * (1.0f / D_) - mean * mean;
        red[0] = mean;
        red[1] = rsqrtf(var + LN_EPS);
    }
    __syncthreads();
    float mean = red[0], rstd = red[1];
    float4 gv = *(const float4*)(g + i0);
    float4 bv = *(const float4*)(b + i0);
    __align__(8) __nv_bfloat16 h[4], l[4];
    #pragma unroll
    for (int j = 0; j < 4; j++) {
        float y = ((&v.x)[j] - mean) * rstd * (&gv.x)[j] + (&bv.x)[j];
        __nv_bfloat16 hh = __float2bfloat16(y);
        h[j] = hh;
        l[j] = __float2bfloat16(y - __bfloat162float(hh));
    }
    *(uint2*)(hi + (size_t)row * D_ + i0) = *(const uint2*)h;
    *(uint2*)(lo + (size_t)row * D_ + i0) = *(const uint2*)l;
}

// ---------------- LoRA down (reads bf16 hi/lo activation) ----------------
__global__ void lora_down_kernel(const __nv_bfloat16* __restrict__ AH,
                                 const __nv_bfloat16* __restrict__ AL,
                                 const float* __restrict__ la1,
                                 const float* __restrict__ la2,
                                 float* __restrict__ t1,
                                 float* __restrict__ t2)
{
    __shared__ float hs[D_];
    const int row = blockIdx.x;
    for (int i = threadIdx.x; i < D_; i += 256)
        hs[i] = __bfloat162float(AH[(size_t)row * D_ + i]) +
                __bfloat162float(AL[(size_t)row * D_ + i]);
    __syncthreads();
    int w = threadIdx.x >> 5, lane = threadIdx.x & 31;
    const float* la; float* t; int r;
    if (w < 4) { la = la1; t = t1; r = w; }
    else       { la = la2; t = t2; r = w - 4; }
    if (la == nullptr) return;
    const float* lar = la + r * D_;
    float s = 0.f;
    for (int i = lane; i < D_; i += 32) s += hs[i] * lar[i];
    #pragma unroll
    for (int o = 16; o >= 1; o >>= 1) s += __shfl_xor_sync(0xffffffffu, s, o);
    if (lane == 0) t[row * 4 + r] = s;
}

// ---------------- flash attention (measured-passing, unchanged) --------------
#define QPAD 68
#define PPAD 36
__global__ void __launch_bounds__(256)
attn_kernel(const float* __restrict__ Q, const float* __restrict__ K,
            const float* __restrict__ V,
            __nv_bfloat16* __restrict__ CH, __nv_bfloat16* __restrict__ CL)
{
    __shared__ float Qs[64 * QPAD];
    __shared__ float Ks[32 * QPAD];
    __shared__ float Vs[32 * QPAD];
    __shared__ float Ps[64 * PPAD];

    const int qt = blockIdx.x & 15;
    const int h  = (blockIdx.x >> 4) & 15;
    const int b  = blockIdx.x >> 8;
    const int tid = threadIdx.x;
    const int ty = tid >> 4, tx = tid & 15;

    const size_t headoff = (size_t)h * HD_;
    const float* qg = Q + ((size_t)(b * S_ + qt * 64)) * D_ + headoff;

    for (int idx = tid; idx < 64 * 64; idx += 256) {
        int r = idx >> 6, c = idx & 63;
        Qs[r * QPAD + c] = qg[(size_t)r * D_ + c] * 0.125f;
    }

    float m[4], l[4], o_acc[4][4];
    #pragma unroll
    for (int i = 0; i < 4; i++) {
        m[i] = -1e30f; l[i] = 0.f;
        #pragma unroll
        for (int j = 0; j < 4; j++) o_acc[i][j] = 0.f;
    }

    for (int kt = 0; kt < S_ / 32; kt++) {
        __syncthreads();
        const float* kg = K + ((size_t)(b * S_ + kt * 32)) * D_ + headoff;
        const float* vg = V + ((size_t)(b * S_ + kt * 32)) * D_ + headoff;
        for (int idx = tid; idx < 32 * 64; idx += 256) {
            int r = idx >> 6, c = idx & 63;
            Ks[r * QPAD + c] = kg[(size_t)r * D_ + c];
            Vs[r * QPAD + c] = vg[(size_t)r * D_ + c];
        }
        __syncthreads();

        float sc[4][2] = {{0.f,0.f},{0.f,0.f},{0.f,0.f},{0.f,0.f}};
        #pragma unroll
        for (int k4 = 0; k4 < 16; k4++) {
            float4 kv0 = *(const float4*)&Ks[(tx * 2 + 0) * QPAD + k4 * 4];
            float4 kv1 = *(const float4*)&Ks[(tx * 2 + 1) * QPAD + k4 * 4];
            #pragma unroll
            for (int i = 0; i < 4; i++) {
                float4 qv = *(const float4*)&Qs[(ty * 4 + i) * QPAD + k4 * 4];
                sc[i][0] += qv.x * kv0.x + qv.y * kv0.y + qv.z * kv0.z + qv.w * kv0.w;
                sc[i][1] += qv.x * kv1.x + qv.y * kv1.y + qv.z * kv1.z + qv.w * kv1.w;
            }
        }

        #pragma unroll
        for (int i = 0; i < 4; i++) {
            float mx = fmaxf(sc[i][0], sc[i][1]);
            #pragma unroll
            for (int o = 8; o >= 1; o >>= 1)
                mx = fmaxf(mx, __shfl_xor_sync(0xffffffffu, mx, o, 16));
            float mnew = fmaxf(m[i], mx);
            float corr = __expf(m[i] - mnew);
            float p0 = __expf(sc[i][0] - mnew);
            float p1 = __expf(sc[i][1] - mnew);
            float rs = p0 + p1;
            #pragma unroll
            for (int o = 8; o >= 1; o >>= 1)
                rs += __shfl_xor_sync(0xffffffffu, rs, o, 16);
            m[i] = mnew;
            l[i] = l[i] * corr + rs;
            #pragma unroll
            for (int j = 0; j < 4; j++) o_acc[i][j] *= corr;
            Ps[(ty * 4 + i) * PPAD + tx * 2 + 0] = p0;
            Ps[(ty * 4 + i) * PPAD + tx * 2 + 1] = p1;
        }
        __syncthreads();

        #pragma unroll
        for (int kk = 0; kk < 32; kk++) {
            float4 vv = *(const float4*)&Vs[kk * QPAD + tx * 4];
            #pragma unroll
            for (int i = 0; i < 4; i++) {
                float p = Ps[(ty * 4 + i) * PPAD + kk];
                o_acc[i][0] += p * vv.x;
                o_acc[i][1] += p * vv.y;
                o_acc[i][2] += p * vv.z;
                o_acc[i][3] += p * vv.w;
            }
        }
    }

    const size_t obase = ((size_t)(b * S_ + qt * 64)) * D_ + headoff;
    #pragma unroll
    for (int i = 0; i < 4; i++) {
        float inv = 1.0f / l[i];
        __align__(8) __nv_bfloat16 hb[4], lbv[4];
        #pragma unroll
        for (int j = 0; j < 4; j++) {
            float v = o_acc[i][j] * inv;
            __nv_bfloat16 hh = __float2bfloat16(v);
            hb[j] = hh;
            lbv[j] = __float2bfloat16(v - __bfloat162float(hh));
        }
        const size_t off = obase + (size_t)(ty * 4 + i) * D_ + tx * 4;
        *(uint2*)(CH + off) = *(const uint2*)hb;
        *(uint2*)(CL + off) = *(const uint2*)lbv;
    }
}

// ---------------- host launch ----------------
extern "C" void kernel_launch(void* const* d_in, const int* in_sizes, int n_in,
                              void* d_out, int out_size)
{
    const float* x      = (const float*)d_in[0];
    const float* Wq     = (const float*)d_in[1];
    const float* bq     = (const float*)d_in[2];
    const float* Wk     = (const float*)d_in[3];
    const float* Wv     = (const float*)d_in[4];
    const float* bv     = (const float*)d_in[5];
    const float* Wo     = (const float*)d_in[6];
    const float* bo     = (const float*)d_in[7];
    const float* la_k   = (const float*)d_in[8];
    const float* lb_k   = (const float*)d_in[9];
    const float* la_v   = (const float*)d_in[10];
    const float* lb_v   = (const float*)d_in[11];
    const float* la_o   = (const float*)d_in[12];
    const float* lb_o   = (const float*)d_in[13];
    const float* g_attn = (const float*)d_in[14];
    const float* b_attn = (const float*)d_in[15];
    const float* W1     = (const float*)d_in[16];
    const float* b1     = (const float*)d_in[17];
    const float* W2     = (const float*)d_in[18];
    const float* b2     = (const float*)d_in[19];
    const float* g_mlp  = (const float*)d_in[20];
    const float* b_mlp  = (const float*)d_in[21];
    float* out = (float*)d_out;

    float *Qf, *Kf, *Vf, *X1, *TK, *TV, *TO;
    __nv_bfloat16 *AH, *AL, *UH, *UL, *WH, *WL;
    cudaGetSymbolAddress((void**)&Qf,  g_qf);
    cudaGetSymbolAddress((void**)&Kf,  g_kf);
    cudaGetSymbolAddress((void**)&Vf,  g_vf);
    cudaGetSymbolAddress((void**)&X1,  g_x1);
    cudaGetSymbolAddress((void**)&TK,  g_tk);
    cudaGetSymbolAddress((void**)&TV,  g_tv);
    cudaGetSymbolAddress((void**)&TO,  g_to);
    cudaGetSymbolAddress((void**)&AH,  g_ah);
    cudaGetSymbolAddress((void**)&AL,  g_al);
    cudaGetSymbolAddress((void**)&UH,  g_uh);
    cudaGetSymbolAddress((void**)&UL,  g_ul);
    cudaGetSymbolAddress((void**)&WH,  g_wh);
    cudaGetSymbolAddress((void**)&WL,  g_wl);

    cudaFuncSetAttribute(gemm_tc<0>, cudaFuncAttributeMaxDynamicSharedMemorySize, GEMM_SMEM);
    cudaFuncSetAttribute(gemm_tc<1>, cudaFuncAttributeMaxDynamicSharedMemorySize, GEMM_SMEM);
    cudaFuncSetAttribute(gemm_tc<2>, cudaFuncAttributeMaxDynamicSharedMemorySize, GEMM_SMEM);
    cudaFuncSetAttribute(gemm_tc<3>, cudaFuncAttributeMaxDynamicSharedMemorySize, GEMM_SMEM);
    cudaFuncSetAttribute(gemm_tc<4>, cudaFuncAttributeMaxDynamicSharedMemorySize, GEMM_SMEM);

    const int MM = 1024 * 1024;
    split_kernel<<<(MM / 4 + 255) / 256, 256>>>(Wq, WH + 0 * MM, WL + 0 * MM, MM / 4);
    split_kernel<<<(MM / 4 + 255) / 256, 256>>>(Wk, WH + 1 * MM, WL + 1 * MM, MM / 4);
    split_kernel<<<(MM / 4 + 255) / 256, 256>>>(Wv, WH + 2 * MM, WL + 2 * MM, MM / 4);
    split_kernel<<<(MM / 4 + 255) / 256, 256>>>(Wo, WH + 3 * MM, WL + 3 * MM, MM / 4);
    split_kernel<<<(MM + 255) / 256, 256>>>(W1, WH + 4 * MM, WL + 4 * MM, MM);
    split_kernel<<<(MM + 255) / 256, 256>>>(W2, WH + 8 * MM, WL + 8 * MM, MM);

    const dim3 gD(D_ / 128, M_ / 128);
    const dim3 gF(DFF_ / 128, M_ / 128);

    // 1. LN1 -> bf16 split
    ln_split_kernel<<<M_, 256>>>(x, g_attn, b_attn, AH, AL);
    // 2. LoRA down for k, v
    lora_down_kernel<<<M_, 256>>>(AH, AL, la_k, la_v, TK, TV);
    // 3-5. Q/K/V projections (rank4 fused for K, V)
    gemm_tc<0><<<gD, 256, GEMM_SMEM>>>(AH, AL, WH + 0 * MM, WL + 0 * MM, bq,      Qf, nullptr, nullptr, nullptr, nullptr, nullptr, M_, D_, D_);
    gemm_tc<2><<<gD, 256, GEMM_SMEM>>>(AH, AL, WH + 1 * MM, WL + 1 * MM, nullptr, Kf, nullptr, nullptr, nullptr, TK, lb_k, M_, D_, D_);
    gemm_tc<2><<<gD, 256, GEMM_SMEM>>>(AH, AL, WH + 2 * MM, WL + 2 * MM, bv,      Vf, nullptr, nullptr, nullptr, TV, lb_v, M_, D_, D_);
    // 6. attention -> ctx bf16 split (overwrites AH/AL)
    attn_kernel<<<B_ * NH_ * (S_ / 64), 256>>>(Qf, Kf, Vf, AH, AL);
    // 7. LoRA down for o
    lora_down_kernel<<<M_, 256>>>(AH, AL, la_o, nullptr, TO, nullptr);
    // 8. O projection: X1 = x + ctx@Wo^T + bo + lora_o
    gemm_tc<3><<<gD, 256, GEMM_SMEM>>>(AH, AL, WH + 3 * MM, WL + 3 * MM, bo, X1, nullptr, nullptr, x, TO, lb_o, M_, D_, D_);
    // 9. LN2 -> bf16 split
    ln_split_kernel<<<M_, 256>>>(X1, g_mlp, b_mlp, AH, AL);
    // 10. MLP1: gelu -> bf16 split
    gemm_tc<1><<<gF, 256, GEMM_SMEM>>>(AH, AL, WH + 4 * MM, WL + 4 * MM, b1, nullptr, UH, UL, nullptr, nullptr, nullptr, M_, DFF_, D_);
    // 11. MLP2: out = X1 + U@W2^T + b2
    gemm_tc<4><<<gD, 256, GEMM_SMEM>>>(UH, UL, WH + 8 * MM, WL + 8 * MM, b2, out, nullptr, nullptr, X1, nullptr, nullptr, M_, D_, DFF_);
}

// round 12
// speedup vs baseline: 1.0401x; 1.0401x over previous
#include <cuda_runtime.h>
#include <cuda_bf16.h>
#include <cmath>
#include <cstdint>

// ---------------- problem constants ----------------
#define B_   8
#define S_   1024
#define D_   1024
#define NH_  16
#define HD_  64
#define M_   (B_ * S_)          // 8192 rows
#define DFF_ (4 * D_)           // 4096
#define LN_EPS 1e-5f
#define LORA_SCALE 0.25f

// ---------------- scratch (device globals) -----------
__device__ float g_qf [M_ * D_];
__device__ float g_kf [M_ * D_];
__device__ float g_vf [M_ * D_];
__device__ float g_x1 [M_ * D_];
__device__ float g_tk [M_ * 4];
__device__ float g_tv [M_ * 4];
__device__ float g_to [M_ * 4];
__device__ __nv_bfloat16 g_ah[M_ * D_];      // activation hi
__device__ __nv_bfloat16 g_al[M_ * D_];      // activation lo
__device__ __nv_bfloat16 g_uh[M_ * DFF_];    // MLP hidden hi
__device__ __nv_bfloat16 g_ul[M_ * DFF_];    // MLP hidden lo
__device__ __nv_bfloat16 g_wh[12 * 1024 * 1024];  // weights hi
__device__ __nv_bfloat16 g_wl[12 * 1024 * 1024];  // weights lo

// ================= helpers =================
__device__ __forceinline__ uint32_t smem_to_u32(const void* p) {
    uint32_t a;
    asm("{ .reg .u64 t; cvta.to.shared.u64 t, %1; cvt.u32.u64 %0, t; }" : "=r"(a) : "l"(p));
    return a;
}
__device__ __forceinline__ void cp_async16(uint32_t dst, const void* src) {
    asm volatile("cp.async.cg.shared.global [%0], [%1], 16;" :: "r"(dst), "l"(src));
}
#define CP_COMMIT()  asm volatile("cp.async.commit_group;" ::: "memory")
#define CP_WAIT0()   asm volatile("cp.async.wait_group 0;" ::: "memory")
#define CP_WAIT1()   asm volatile("cp.async.wait_group 1;" ::: "memory")

#define MMA_BF16(d, a, b)                                                      \
    asm volatile(                                                              \
        "mma.sync.aligned.m16n8k16.row.col.f32.bf16.bf16.f32 "                 \
        "{%0,%1,%2,%3}, {%4,%5,%6,%7}, {%8,%9}, {%0,%1,%2,%3};"                \
        : "+f"((d)[0]), "+f"((d)[1]), "+f"((d)[2]), "+f"((d)[3])               \
        : "r"((a)[0]), "r"((a)[1]), "r"((a)[2]), "r"((a)[3]),                  \
          "r"((b)[0]), "r"((b)[1]))

// ================= mma.sync GEMM (3-pass bf16 split) =================
// Mainloop byte-identical to the measured 3410us kernel (scalar fragment loads,
// CP_WAIT1 two-barrier pipeline). THIS ROUND's only change: min-blocks=2 in
// __launch_bounds__ for 2 CTAs/SM (smem 2x81920=160KB fits; regs capped 128).
// EPI: 0 = fp32 +bias | 1 = gelu->bf16 split | 2 = +bias? +rank4 |
//      3 = resid + bias + rank4 | 4 = resid + bias
#define SROW 40                       // halves per smem row (80B)
#define TILE_B (128 * SROW * 2)       // 10240 bytes
#define STAGE_B (4 * TILE_B)
#define GEMM_SMEM (2 * STAGE_B)       // 81920

template<int EPI>
__global__ void __launch_bounds__(256, 2)
gemm_tc(const __nv_bfloat16* __restrict__ Ah, const __nv_bfloat16* __restrict__ Al,
        const __nv_bfloat16* __restrict__ Bh, const __nv_bfloat16* __restrict__ Bl,
        const float* __restrict__ bias, float* __restrict__ C,
        __nv_bfloat16* __restrict__ Ch, __nv_bfloat16* __restrict__ Cl,
        const float* __restrict__ resid, const float* __restrict__ t4,
        const float* __restrict__ lb,
        int M, int N, int K)
{
    extern __shared__ char sm[];
    const uint32_t smem_u32 = smem_to_u32(sm);
    const int tid  = threadIdx.x;
    const int lane = tid & 31;
    const int g    = lane >> 2, tg = lane & 3;
    const int w    = tid >> 5;
    const int wm   = w >> 2;          // 0..1
    const int wn   = w & 3;           // 0..3
    const int bm   = blockIdx.y * 128, bn = blockIdx.x * 128;

    const size_t rowb = (size_t)K * 2;
    const char* srcA_h = (const char*)(Ah + (size_t)bm * K);
    const char* srcA_l = (const char*)(Al + (size_t)bm * K);
    const char* srcB_h = (const char*)(Bh + (size_t)bn * K);
    const char* srcB_l = (const char*)(Bl + (size_t)bn * K);

    const int NC = K >> 5;                 // K / 32

    auto load_chunk = [&](int c, int s) {
        const uint32_t sb = smem_u32 + s * STAGE_B;
        const size_t coff = (size_t)c * 64;
        #pragma unroll
        for (int t = 0; t < 2; t++) {
            const int unit = tid + t * 256;
            const int row = unit >> 2, cb = unit & 3;
            const size_t so = (size_t)row * rowb + coff + cb * 16;
            const uint32_t doff = row * 80 + cb * 16;
            cp_async16(sb + 0 * TILE_B + doff, srcA_h + so);
            cp_async16(sb + 1 * TILE_B + doff, srcA_l + so);
            cp_async16(sb + 2 * TILE_B + doff, srcB_h + so);
            cp_async16(sb + 3 * TILE_B + doff, srcB_l + so);
        }
        CP_COMMIT();
    };

    float acc[4][4][4];
    #pragma unroll
    for (int mi = 0; mi < 4; mi++)
        #pragma unroll
        for (int ni = 0; ni < 4; ni++)
            #pragma unroll
            for (int q = 0; q < 4; q++) acc[mi][ni][q] = 0.f;

    load_chunk(0, 0);

    for (int c = 0; c < NC; c++) {
        const int s = c & 1;
        if (c + 1 < NC) { load_chunk(c + 1, (c + 1) & 1); CP_WAIT1(); }
        else            { CP_WAIT0(); }
        __syncthreads();

        const __nv_bfloat16* sA_h = (const __nv_bfloat16*)(sm + s * STAGE_B + 0 * TILE_B);
        const __nv_bfloat16* sA_l = (const __nv_bfloat16*)(sm + s * STAGE_B + 1 * TILE_B);
        const __nv_bfloat16* sB_h = (const __nv_bfloat16*)(sm + s * STAGE_B + 2 * TILE_B);
        const __nv_bfloat16* sB_l = (const __nv_bfloat16*)(sm + s * STAGE_B + 3 * TILE_B);

        #pragma unroll
        for (int ks = 0; ks < 2; ks++) {
            const int kc = ks * 16 + 2 * tg;
            uint32_t bh[4][2], bl[4][2];
            #pragma unroll
            for (int ni = 0; ni < 4; ni++) {
                const int n = wn * 32 + ni * 8 + g;
                bh[ni][0] = *(const uint32_t*)(sB_h + n * SROW + kc);
                bh[ni][1] = *(const uint32_t*)(sB_h + n * SROW + kc + 8);
                bl[ni][0] = *(const uint32_t*)(sB_l + n * SROW + kc);
                bl[ni][1] = *(const uint32_t*)(sB_l + n * SROW + kc + 8);
            }
            #pragma unroll
            for (int mi = 0; mi < 4; mi++) {
                const int r0 = wm * 64 + mi * 16 + g;
                uint32_t ah[4], al[4];
                ah[0] = *(const uint32_t*)(sA_h + r0 * SROW + kc);
                ah[1] = *(const uint32_t*)(sA_h + (r0 + 8) * SROW + kc);
                ah[2] = *(const uint32_t*)(sA_h + r0 * SROW + kc + 8);
                ah[3] = *(const uint32_t*)(sA_h + (r0 + 8) * SROW + kc + 8);
                al[0] = *(const uint32_t*)(sA_l + r0 * SROW + kc);
                al[1] = *(const uint32_t*)(sA_l + (r0 + 8) * SROW + kc);
                al[2] = *(const uint32_t*)(sA_l + r0 * SROW + kc + 8);
                al[3] = *(const uint32_t*)(sA_l + (r0 + 8) * SROW + kc + 8);
                #pragma unroll
                for (int ni = 0; ni < 4; ni++) {
                    MMA_BF16(acc[mi][ni], ah, bh[ni]);
                    MMA_BF16(acc[mi][ni], ah, bl[ni]);
                    MMA_BF16(acc[mi][ni], al, bh[ni]);
                }
            }
        }
        __syncthreads();
    }

    // ---- fused epilogue (identical to measured 3410us kernel) ----
    #pragma unroll
    for (int mi = 0; mi < 4; mi++) {
        const int row0 = bm + wm * 64 + mi * 16 + g;
        float4 tr0, tr1;
        if (EPI == 2 || EPI == 3) {
            tr0 = *(const float4*)(t4 + (size_t)row0 * 4);
            tr1 = *(const float4*)(t4 + (size_t)(row0 + 8) * 4);
        }
        #pragma unroll
        for (int ni = 0; ni < 4; ni++) {
            const int col = bn + wn * 32 + ni * 8 + 2 * tg;
            const float bx = bias ? bias[col]     : 0.f;
            const float by = bias ? bias[col + 1] : 0.f;
            float v0 = acc[mi][ni][0] + bx, v1 = acc[mi][ni][1] + by;
            float v2 = acc[mi][ni][2] + bx, v3 = acc[mi][ni][3] + by;
            if (EPI == 2 || EPI == 3) {
                float4 c0 = *(const float4*)(lb + (size_t)col * 4);
                float4 c1 = *(const float4*)(lb + (size_t)(col + 1) * 4);
                v0 += LORA_SCALE * (tr0.x*c0.x + tr0.y*c0.y + tr0.z*c0.z + tr0.w*c0.w);
                v1 += LORA_SCALE * (tr0.x*c1.x + tr0.y*c1.y + tr0.z*c1.z + tr0.w*c1.w);
                v2 += LORA_SCALE * (tr1.x*c0.x + tr1.y*c0.y + tr1.z*c0.z + tr1.w*c0.w);
                v3 += LORA_SCALE * (tr1.x*c1.x + tr1.y*c1.y + tr1.z*c1.z + tr1.w*c1.w);
            }
            if (EPI == 3 || EPI == 4) {
                v0 += resid[(size_t)row0 * N + col];
                v1 += resid[(size_t)row0 * N + col + 1];
                v2 += resid[(size_t)(row0 + 8) * N + col];
                v3 += resid[(size_t)(row0 + 8) * N + col + 1];
            }
            if (EPI == 1) {
                v0 = 0.5f * v0 * (1.0f + erff(v0 * 0.70710678118654752f));
                v1 = 0.5f * v1 * (1.0f + erff(v1 * 0.70710678118654752f));
                v2 = 0.5f * v2 * (1.0f + erff(v2 * 0.70710678118654752f));
                v3 = 0.5f * v3 * (1.0f + erff(v3 * 0.70710678118654752f));
                __nv_bfloat16 h0 = __float2bfloat16(v0), h1 = __float2bfloat16(v1);
                __nv_bfloat16 h2 = __float2bfloat16(v2), h3 = __float2bfloat16(v3);
                __nv_bfloat162 hp0 = {h0, h1}, hp1 = {h2, h3};
                __nv_bfloat162 lp0 = {__float2bfloat16(v0 - __bfloat162float(h0)),
                                      __float2bfloat16(v1 - __bfloat162float(h1))};
                __nv_bfloat162 lp1 = {__float2bfloat16(v2 - __bfloat162float(h2)),
                                      __float2bfloat16(v3 - __bfloat162float(h3))};
                *(uint32_t*)(Ch + (size_t)row0 * N + col)       = *(uint32_t*)&hp0;
                *(uint32_t*)(Ch + (size_t)(row0 + 8) * N + col) = *(uint32_t*)&hp1;
                *(uint32_t*)(Cl + (size_t)row0 * N + col)       = *(uint32_t*)&lp0;
                *(uint32_t*)(Cl + (size_t)(row0 + 8) * N + col) = *(uint32_t*)&lp1;
            } else {
                *(float2*)(C + (size_t)row0 * N + col)       = make_float2(v0, v1);
                *(float2*)(C + (size_t)(row0 + 8) * N + col) = make_float2(v2, v3);
            }
        }
    }
}

// ---------------- weight fp32 -> bf16 hi/lo split ----------------
__global__ void split_kernel(const float* __restrict__ in,
                             __nv_bfloat16* __restrict__ hi,
                             __nv_bfloat16* __restrict__ lo, int n4)
{
    int i = blockIdx.x * blockDim.x + threadIdx.x;
    if (i >= n4) return;
    float4 v = ((const float4*)in)[i];
    __align__(8) __nv_bfloat16 h[4], l[4];
    #pragma unroll
    for (int j = 0; j < 4; j++) {
        float x = (&v.x)[j];
        __nv_bfloat16 hh = __float2bfloat16(x);
        h[j] = hh;
        l[j] = __float2bfloat16(x - __bfloat162float(hh));
    }
    ((uint2*)hi)[i] = *(const uint2*)h;
    ((uint2*)lo)[i] = *(const uint2*)l;
}

// ---------------- fused LayerNorm + bf16 split ----------------
__global__ void ln_split_kernel(const float* __restrict__ x,
                                const float* __restrict__ g,
                                const float* __restrict__ b,
                                __nv_bfloat16* __restrict__ hi,
                                __nv_bfloat16* __restrict__ lo)
{
    __shared__ float red[16];
    const int row = blockIdx.x;
    const int i0 = threadIdx.x * 4;
    const float* xr = x + (size_t)row * D_;
    float4 v = *(const float4*)(xr + i0);
    float s  = v.x + v.y + v.z + v.w;
    float sq = v.x*v.x + v.y*v.y + v.z*v.z + v.w*v.w;
    #pragma unroll
    for (int o = 16; o >= 1; o >>= 1) {
        s  += __shfl_xor_sync(0xffffffffu, s,  o);
        sq += __shfl_xor_sync(0xffffffffu, sq, o);
    }
    int w = threadIdx.x >> 5, lane = threadIdx.x & 31;
    if (lane == 0) { red[w] = s; red[w + 8] = sq; }
    __syncthreads();
    if (threadIdx.x == 0) {
        float ts = 0.f, tq = 0.f;
        #pragma unroll
        for (int i = 0; i < 8; i++) { ts += red[i]; tq += red[i + 8]; }
        float mean = ts * (1.0f / D_);
        float var  = tq * (1.0f / D_) - mean * mean;
        red[0] = mean;
        red[1] = rsqrtf(var + LN_EPS);
    }
    __syncthreads();
    float mean = red[0], rstd = red[1];
    float4 gv = *(const float4*)(g + i0);
    float4 bv = *(const float4*)(b + i0);
    __align__(8) __nv_bfloat16 h[4], l[4];
    #pragma unroll
    for (int j = 0; j < 4; j++) {
        float y = ((&v.x)[j] - mean) * rstd * (&gv.x)[j] + (&bv.x)[j];
        __nv_bfloat16 hh = __float2bfloat16(y);
        h[j] = hh;
        l[j] = __float2bfloat16(y - __bfloat162float(hh));
    }
    *(uint2*)(hi + (size_t)row * D_ + i0) = *(const uint2*)h;
    *(uint2*)(lo + (size_t)row * D_ + i0) = *(const uint2*)l;
}

// ---------------- LoRA down (reads bf16 hi/lo activation) ----------------
__global__ void lora_down_kernel(const __nv_bfloat16* __restrict__ AH,
                                 const __nv_bfloat16* __restrict__ AL,
                                 const float* __restrict__ la1,
                                 const float* __restrict__ la2,
                                 float* __restrict__ t1,
                                 float* __restrict__ t2)
{
    __shared__ float hs[D_];
    const int row = blockIdx.x;
    for (int i = threadIdx.x; i < D_; i += 256)
        hs[i] = __bfloat162float(AH[(size_t)row * D_ + i]) +
                __bfloat162float(AL[(size_t)row * D_ + i]);
    __syncthreads();
    int w = threadIdx.x >> 5, lane = threadIdx.x & 31;
    const float* la; float* t; int r;
    if (w < 4) { la = la1; t = t1; r = w; }
    else       { la = la2; t = t2; r = w - 4; }
    if (la == nullptr) return;
    const float* lar = la + r * D_;
    float s = 0.f;
    for (int i = lane; i < D_; i += 32) s += hs[i] * lar[i];
    #pragma unroll
    for (int o = 16; o >= 1; o >>= 1) s += __shfl_xor_sync(0xffffffffu, s, o);
    if (lane == 0) t[row * 4 + r] = s;
}

// ---------------- flash attention (measured-passing, unchanged) --------------
#define QPAD 68
#define PPAD 36
__global__ void __launch_bounds__(256)
attn_kernel(const float* __restrict__ Q, const float* __restrict__ K,
            const float* __restrict__ V,
            __nv_bfloat16* __restrict__ CH, __nv_bfloat16* __restrict__ CL)
{
    __shared__ float Qs[64 * QPAD];
    __shared__ float Ks[32 * QPAD];
    __shared__ float Vs[32 * QPAD];
    __shared__ float Ps[64 * PPAD];

    const int qt = blockIdx.x & 15;
    const int h  = (blockIdx.x >> 4) & 15;
    const int b  = blockIdx.x >> 8;
    const int tid = threadIdx.x;
    const int ty = tid >> 4, tx = tid & 15;

    const size_t headoff = (size_t)h * HD_;
    const float* qg = Q + ((size_t)(b * S_ + qt * 64)) * D_ + headoff;

    for (int idx = tid; idx < 64 * 64; idx += 256) {
        int r = idx >> 6, c = idx & 63;
        Qs[r * QPAD + c] = qg[(size_t)r * D_ + c] * 0.125f;
    }

    float m[4], l[4], o_acc[4][4];
    #pragma unroll
    for (int i = 0; i < 4; i++) {
        m[i] = -1e30f; l[i] = 0.f;
        #pragma unroll
        for (int j = 0; j < 4; j++) o_acc[i][j] = 0.f;
    }

    for (int kt = 0; kt < S_ / 32; kt++) {
        __syncthreads();
        const float* kg = K + ((size_t)(b * S_ + kt * 32)) * D_ + headoff;
        const float* vg = V + ((size_t)(b * S_ + kt * 32)) * D_ + headoff;
        for (int idx = tid; idx < 32 * 64; idx += 256) {
            int r = idx >> 6, c = idx & 63;
            Ks[r * QPAD + c] = kg[(size_t)r * D_ + c];
            Vs[r * QPAD + c] = vg[(size_t)r * D_ + c];
        }
        __syncthreads();

        float sc[4][2] = {{0.f,0.f},{0.f,0.f},{0.f,0.f},{0.f,0.f}};
        #pragma unroll
        for (int k4 = 0; k4 < 16; k4++) {
            float4 kv0 = *(const float4*)&Ks[(tx * 2 + 0) * QPAD + k4 * 4];
            float4 kv1 = *(const float4*)&Ks[(tx * 2 + 1) * QPAD + k4 * 4];
            #pragma unroll
            for (int i = 0; i < 4; i++) {
                float4 qv = *(const float4*)&Qs[(ty * 4 + i) * QPAD + k4 * 4];
                sc[i][0] += qv.x * kv0.x + qv.y * kv0.y + qv.z * kv0.z + qv.w * kv0.w;
                sc[i][1] += qv.x * kv1.x + qv.y * kv1.y + qv.z * kv1.z + qv.w * kv1.w;
            }
        }

        #pragma unroll
        for (int i = 0; i < 4; i++) {
            float mx = fmaxf(sc[i][0], sc[i][1]);
            #pragma unroll
            for (int o = 8; o >= 1; o >>= 1)
                mx = fmaxf(mx, __shfl_xor_sync(0xffffffffu, mx, o, 16));
            float mnew = fmaxf(m[i], mx);
            float corr = __expf(m[i] - mnew);
            float p0 = __expf(sc[i][0] - mnew);
            float p1 = __expf(sc[i][1] - mnew);
            float rs = p0 + p1;
            #pragma unroll
            for (int o = 8; o >= 1; o >>= 1)
                rs += __shfl_xor_sync(0xffffffffu, rs, o, 16);
            m[i] = mnew;
            l[i] = l[i] * corr + rs;
            #pragma unroll
            for (int j = 0; j < 4; j++) o_acc[i][j] *= corr;
            Ps[(ty * 4 + i) * PPAD + tx * 2 + 0] = p0;
            Ps[(ty * 4 + i) * PPAD + tx * 2 + 1] = p1;
        }
        __syncthreads();

        #pragma unroll
        for (int kk = 0; kk < 32; kk++) {
            float4 vv = *(const float4*)&Vs[kk * QPAD + tx * 4];
            #pragma unroll
            for (int i = 0; i < 4; i++) {
                float p = Ps[(ty * 4 + i) * PPAD + kk];
                o_acc[i][0] += p * vv.x;
                o_acc[i][1] += p * vv.y;
                o_acc[i][2] += p * vv.z;
                o_acc[i][3] += p * vv.w;
            }
        }
    }

    const size_t obase = ((size_t)(b * S_ + qt * 64)) * D_ + headoff;
    #pragma unroll
    for (int i = 0; i < 4; i++) {
        float inv = 1.0f / l[i];
        __align__(8) __nv_bfloat16 hb[4], lbv[4];
        #pragma unroll
        for (int j = 0; j < 4; j++) {
            float v = o_acc[i][j] * inv;
            __nv_bfloat16 hh = __float2bfloat16(v);
            hb[j] = hh;
            lbv[j] = __float2bfloat16(v - __bfloat162float(hh));
        }
        const size_t off = obase + (size_t)(ty * 4 + i) * D_ + tx * 4;
        *(uint2*)(CH + off) = *(const uint2*)hb;
        *(uint2*)(CL + off) = *(const uint2*)lbv;
    }
}

// ---------------- host launch ----------------
extern "C" void kernel_launch(void* const* d_in, const int* in_sizes, int n_in,
                              void* d_out, int out_size)
{
    const float* x      = (const float*)d_in[0];
    const float* Wq     = (const float*)d_in[1];
    const float* bq     = (const float*)d_in[2];
    const float* Wk     = (const float*)d_in[3];
    const float* Wv     = (const float*)d_in[4];
    const float* bv     = (const float*)d_in[5];
    const float* Wo     = (const float*)d_in[6];
    const float* bo     = (const float*)d_in[7];
    const float* la_k   = (const float*)d_in[8];
    const float* lb_k   = (const float*)d_in[9];
    const float* la_v   = (const float*)d_in[10];
    const float* lb_v   = (const float*)d_in[11];
    const float* la_o   = (const float*)d_in[12];
    const float* lb_o   = (const float*)d_in[13];
    const float* g_attn = (const float*)d_in[14];
    const float* b_attn = (const float*)d_in[15];
    const float* W1     = (const float*)d_in[16];
    const float* b1     = (const float*)d_in[17];
    const float* W2     = (const float*)d_in[18];
    const float* b2     = (const float*)d_in[19];
    const float* g_mlp  = (const float*)d_in[20];
    const float* b_mlp  = (const float*)d_in[21];
    float* out = (float*)d_out;

    float *Qf, *Kf, *Vf, *X1, *TK, *TV, *TO;
    __nv_bfloat16 *AH, *AL, *UH, *UL, *WH, *WL;
    cudaGetSymbolAddress((void**)&Qf,  g_qf);
    cudaGetSymbolAddress((void**)&Kf,  g_kf);
    cudaGetSymbolAddress((void**)&Vf,  g_vf);
    cudaGetSymbolAddress((void**)&X1,  g_x1);
    cudaGetSymbolAddress((void**)&TK,  g_tk);
    cudaGetSymbolAddress((void**)&TV,  g_tv);
    cudaGetSymbolAddress((void**)&TO,  g_to);
    cudaGetSymbolAddress((void**)&AH,  g_ah);
    cudaGetSymbolAddress((void**)&AL,  g_al);
    cudaGetSymbolAddress((void**)&UH,  g_uh);
    cudaGetSymbolAddress((void**)&UL,  g_ul);
    cudaGetSymbolAddress((void**)&WH,  g_wh);
    cudaGetSymbolAddress((void**)&WL,  g_wl);

    cudaFuncSetAttribute(gemm_tc<0>, cudaFuncAttributeMaxDynamicSharedMemorySize, GEMM_SMEM);
    cudaFuncSetAttribute(gemm_tc<1>, cudaFuncAttributeMaxDynamicSharedMemorySize, GEMM_SMEM);
    cudaFuncSetAttribute(gemm_tc<2>, cudaFuncAttributeMaxDynamicSharedMemorySize, GEMM_SMEM);
    cudaFuncSetAttribute(gemm_tc<3>, cudaFuncAttributeMaxDynamicSharedMemorySize, GEMM_SMEM);
    cudaFuncSetAttribute(gemm_tc<4>, cudaFuncAttributeMaxDynamicSharedMemorySize, GEMM_SMEM);

    const int MM = 1024 * 1024;
    split_kernel<<<(MM / 4 + 255) / 256, 256>>>(Wq, WH + 0 * MM, WL + 0 * MM, MM / 4);
    split_kernel<<<(MM / 4 + 255) / 256, 256>>>(Wk, WH + 1 * MM, WL + 1 * MM, MM / 4);
    split_kernel<<<(MM / 4 + 255) / 256, 256>>>(Wv, WH + 2 * MM, WL + 2 * MM, MM / 4);
    split_kernel<<<(MM / 4 + 255) / 256, 256>>>(Wo, WH + 3 * MM, WL + 3 * MM, MM / 4);
    split_kernel<<<(MM + 255) / 256, 256>>>(W1, WH + 4 * MM, WL + 4 * MM, MM);
    split_kernel<<<(MM + 255) / 256, 256>>>(W2, WH + 8 * MM, WL + 8 * MM, MM);

    const dim3 gD(D_ / 128, M_ / 128);
    const dim3 gF(DFF_ / 128, M_ / 128);

    // 1. LN1 -> bf16 split
    ln_split_kernel<<<M_, 256>>>(x, g_attn, b_attn, AH, AL);
    // 2. LoRA down for k, v
    lora_down_kernel<<<M_, 256>>>(AH, AL, la_k, la_v, TK, TV);
    // 3-5. Q/K/V projections (rank4 fused for K, V)
    gemm_tc<0><<<gD, 256, GEMM_SMEM>>>(AH, AL, WH + 0 * MM, WL + 0 * MM, bq,      Qf, nullptr, nullptr, nullptr, nullptr, nullptr, M_, D_, D_);
    gemm_tc<2><<<gD, 256, GEMM_SMEM>>>(AH, AL, WH + 1 * MM, WL + 1 * MM, nullptr, Kf, nullptr, nullptr, nullptr, TK, lb_k, M_, D_, D_);
    gemm_tc<2><<<gD, 256, GEMM_SMEM>>>(AH, AL, WH + 2 * MM, WL + 2 * MM, bv,      Vf, nullptr, nullptr, nullptr, TV, lb_v, M_, D_, D_);
    // 6. attention -> ctx bf16 split (overwrites AH/AL)
    attn_kernel<<<B_ * NH_ * (S_ / 64), 256>>>(Qf, Kf, Vf, AH, AL);
    // 7. LoRA down for o
    lora_down_kernel<<<M_, 256>>>(AH, AL, la_o, nullptr, TO, nullptr);
    // 8. O projection: X1 = x + ctx@Wo^T + bo + lora_o
    gemm_tc<3><<<gD, 256, GEMM_SMEM>>>(AH, AL, WH + 3 * MM, WL + 3 * MM, bo, X1, nullptr, nullptr, x, TO, lb_o, M_, D_, D_);
    // 9. LN2 -> bf16 split
    ln_split_kernel<<<M_, 256>>>(X1, g_mlp, b_mlp, AH, AL);
    // 10. MLP1: gelu -> bf16 split
    gemm_tc<1><<<gF, 256, GEMM_SMEM>>>(AH, AL, WH + 4 * MM, WL + 4 * MM, b1, nullptr, UH, UL, nullptr, nullptr, nullptr, M_, DFF_, D_);
    // 11. MLP2: out = X1 + U@W2^T + b2
    gemm_tc<4><<<gD, 256, GEMM_SMEM>>>(UH, UL, WH + 8 * MM, WL + 8 * MM, b2, out, nullptr, nullptr, X1, nullptr, nullptr, M_, D_, DFF_);
}

// round 14
// speedup vs baseline: 1.2499x; 1.2017x over previous
#include <cuda_runtime.h>
#include <cuda_fp16.h>
#include <cmath>
#include <cstdint>

// ---------------- problem constants ----------------
#define B_   8
#define S_   1024
#define D_   1024
#define NH_  16
#define HD_  64
#define M_   (B_ * S_)          // 8192 rows
#define DFF_ (4 * D_)           // 4096
#define LN_EPS 1e-5f
#define LORA_SCALE 0.25f

// ---------------- scratch (device globals) -----------
__device__ float g_qf [M_ * D_];
__device__ float g_kf [M_ * D_];
__device__ float g_vf [M_ * D_];
__device__ float g_x1 [M_ * D_];
__device__ float g_tk [M_ * 4];
__device__ float g_tv [M_ * 4];
__device__ float g_to [M_ * 4];
__device__ __half g_ah[M_ * D_];      // activation hi (fp16)
__device__ __half g_al[M_ * D_];      // activation lo (fp16)
__device__ __half g_uh[M_ * DFF_];    // MLP hidden hi
__device__ __half g_ul[M_ * DFF_];    // MLP hidden lo
__device__ __half g_wh[12 * 1024 * 1024];  // weights fp16 (Wq,Wk,Wv,Wo,W1,W2)

// ================= helpers =================
__device__ __forceinline__ uint32_t smem_to_u32(const void* p) {
    uint32_t a;
    asm("{ .reg .u64 t; cvta.to.shared.u64 t, %1; cvt.u32.u64 %0, t; }" : "=r"(a) : "l"(p));
    return a;
}
__device__ __forceinline__ void cp_async16(uint32_t dst, const void* src) {
    asm volatile("cp.async.cg.shared.global [%0], [%1], 16;" :: "r"(dst), "l"(src));
}
#define CP_COMMIT()  asm volatile("cp.async.commit_group;" ::: "memory")
#define CP_WAIT0()   asm volatile("cp.async.wait_group 0;" ::: "memory")
#define CP_WAIT1()   asm volatile("cp.async.wait_group 1;" ::: "memory")

#define MMA_F16(d, a, b)                                                       \
    asm volatile(                                                              \
        "mma.sync.aligned.m16n8k16.row.col.f32.f16.f16.f32 "                   \
        "{%0,%1,%2,%3}, {%4,%5,%6,%7}, {%8,%9}, {%0,%1,%2,%3};"                \
        : "+f"((d)[0]), "+f"((d)[1]), "+f"((d)[2]), "+f"((d)[3])               \
        : "r"((a)[0]), "r"((a)[1]), "r"((a)[2]), "r"((a)[3]),                  \
          "r"((b)[0]), "r"((b)[1]))

// ================= mma.sync GEMM (2-pass fp16 split) =================
// C = (Ah+Al) @ Bh^T : A split in fp16 (2^-22), B single fp16 (2^-11).
// Pipeline/occupancy identical to the measured 3333us kernel.
// EPI: 0 = fp32 +bias | 1 = gelu->fp16 split | 2 = +bias? +rank4 |
//      3 = resid + bias + rank4 | 4 = resid + bias
#define SROW 40                       // halves per smem row (80B)
#define TILE_B (128 * SROW * 2)       // 10240 bytes
#define STAGE_B (3 * TILE_B)          // Ah, Al, Bh
#define GEMM_SMEM (2 * STAGE_B)       // 61440

template<int EPI>
__global__ void __launch_bounds__(256, 2)
gemm_tc(const __half* __restrict__ Ah, const __half* __restrict__ Al,
        const __half* __restrict__ Bh,
        const float* __restrict__ bias, float* __restrict__ C,
        __half* __restrict__ Ch, __half* __restrict__ Cl,
        const float* __restrict__ resid, const float* __restrict__ t4,
        const float* __restrict__ lb,
        int M, int N, int K)
{
    extern __shared__ char sm[];
    const uint32_t smem_u32 = smem_to_u32(sm);
    const int tid  = threadIdx.x;
    const int lane = tid & 31;
    const int g    = lane >> 2, tg = lane & 3;
    const int w    = tid >> 5;
    const int wm   = w >> 2;          // 0..1
    const int wn   = w & 3;           // 0..3
    const int bm   = blockIdx.y * 128, bn = blockIdx.x * 128;

    const size_t rowb = (size_t)K * 2;
    const char* srcA_h = (const char*)(Ah + (size_t)bm * K);
    const char* srcA_l = (const char*)(Al + (size_t)bm * K);
    const char* srcB_h = (const char*)(Bh + (size_t)bn * K);

    const int NC = K >> 5;                 // K / 32

    auto load_chunk = [&](int c, int s) {
        const uint32_t sb = smem_u32 + s * STAGE_B;
        const size_t coff = (size_t)c * 64;
        #pragma unroll
        for (int t = 0; t < 2; t++) {
            const int unit = tid + t * 256;
            const int row = unit >> 2, cb = unit & 3;
            const size_t so = (size_t)row * rowb + coff + cb * 16;
            const uint32_t doff = row * 80 + cb * 16;
            cp_async16(sb + 0 * TILE_B + doff, srcA_h + so);
            cp_async16(sb + 1 * TILE_B + doff, srcA_l + so);
            cp_async16(sb + 2 * TILE_B + doff, srcB_h + so);
        }
        CP_COMMIT();
    };

    float acc[4][4][4];
    #pragma unroll
    for (int mi = 0; mi < 4; mi++)
        #pragma unroll
        for (int ni = 0; ni < 4; ni++)
            #pragma unroll
            for (int q = 0; q < 4; q++) acc[mi][ni][q] = 0.f;

    load_chunk(0, 0);

    for (int c = 0; c < NC; c++) {
        const int s = c & 1;
        if (c + 1 < NC) { load_chunk(c + 1, (c + 1) & 1); CP_WAIT1(); }
        else            { CP_WAIT0(); }
        __syncthreads();

        const __half* sA_h = (const __half*)(sm + s * STAGE_B + 0 * TILE_B);
        const __half* sA_l = (const __half*)(sm + s * STAGE_B + 1 * TILE_B);
        const __half* sB_h = (const __half*)(sm + s * STAGE_B + 2 * TILE_B);

        #pragma unroll
        for (int ks = 0; ks < 2; ks++) {
            const int kc = ks * 16 + 2 * tg;
            uint32_t bh[4][2];
            #pragma unroll
            for (int ni = 0; ni < 4; ni++) {
                const int n = wn * 32 + ni * 8 + g;
                bh[ni][0] = *(const uint32_t*)(sB_h + n * SROW + kc);
                bh[ni][1] = *(const uint32_t*)(sB_h + n * SROW + kc + 8);
            }
            #pragma unroll
            for (int mi = 0; mi < 4; mi++) {
                const int r0 = wm * 64 + mi * 16 + g;
                uint32_t ah[4], al[4];
                ah[0] = *(const uint32_t*)(sA_h + r0 * SROW + kc);
                ah[1] = *(const uint32_t*)(sA_h + (r0 + 8) * SROW + kc);
                ah[2] = *(const uint32_t*)(sA_h + r0 * SROW + kc + 8);
                ah[3] = *(const uint32_t*)(sA_h + (r0 + 8) * SROW + kc + 8);
                al[0] = *(const uint32_t*)(sA_l + r0 * SROW + kc);
                al[1] = *(const uint32_t*)(sA_l + (r0 + 8) * SROW + kc);
                al[2] = *(const uint32_t*)(sA_l + r0 * SROW + kc + 8);
                al[3] = *(const uint32_t*)(sA_l + (r0 + 8) * SROW + kc + 8);
                #pragma unroll
                for (int ni = 0; ni < 4; ni++) {
                    MMA_F16(acc[mi][ni], ah, bh[ni]);
                    MMA_F16(acc[mi][ni], al, bh[ni]);
                }
            }
        }
        __syncthreads();
    }

    // ---- fused epilogue ----
    #pragma unroll
    for (int mi = 0; mi < 4; mi++) {
        const int row0 = bm + wm * 64 + mi * 16 + g;
        float4 tr0, tr1;
        if (EPI == 2 || EPI == 3) {
            tr0 = *(const float4*)(t4 + (size_t)row0 * 4);
            tr1 = *(const float4*)(t4 + (size_t)(row0 + 8) * 4);
        }
        #pragma unroll
        for (int ni = 0; ni < 4; ni++) {
            const int col = bn + wn * 32 + ni * 8 + 2 * tg;
            const float bx = bias ? bias[col]     : 0.f;
            const float by = bias ? bias[col + 1] : 0.f;
            float v0 = acc[mi][ni][0] + bx, v1 = acc[mi][ni][1] + by;
            float v2 = acc[mi][ni][2] + bx, v3 = acc[mi][ni][3] + by;
            if (EPI == 2 || EPI == 3) {
                float4 c0 = *(const float4*)(lb + (size_t)col * 4);
                float4 c1 = *(const float4*)(lb + (size_t)(col + 1) * 4);
                v0 += LORA_SCALE * (tr0.x*c0.x + tr0.y*c0.y + tr0.z*c0.z + tr0.w*c0.w);
                v1 += LORA_SCALE * (tr0.x*c1.x + tr0.y*c1.y + tr0.z*c1.z + tr0.w*c1.w);
                v2 += LORA_SCALE * (tr1.x*c0.x + tr1.y*c0.y + tr1.z*c0.z + tr1.w*c0.w);
                v3 += LORA_SCALE * (tr1.x*c1.x + tr1.y*c1.y + tr1.z*c1.z + tr1.w*c1.w);
            }
            if (EPI == 3 || EPI == 4) {
                v0 += resid[(size_t)row0 * N + col];
                v1 += resid[(size_t)row0 * N + col + 1];
                v2 += resid[(size_t)(row0 + 8) * N + col];
                v3 += resid[(size_t)(row0 + 8) * N + col + 1];
            }
            if (EPI == 1) {
                v0 = 0.5f * v0 * (1.0f + erff(v0 * 0.70710678118654752f));
                v1 = 0.5f * v1 * (1.0f + erff(v1 * 0.70710678118654752f));
                v2 = 0.5f * v2 * (1.0f + erff(v2 * 0.70710678118654752f));
                v3 = 0.5f * v3 * (1.0f + erff(v3 * 0.70710678118654752f));
                __half h0 = __float2half_rn(v0), h1 = __float2half_rn(v1);
                __half h2 = __float2half_rn(v2), h3 = __float2half_rn(v3);
                __half2 hp0 = {h0, h1}, hp1 = {h2, h3};
                __half2 lp0 = {__float2half_rn(v0 - __half2float(h0)),
                               __float2half_rn(v1 - __half2float(h1))};
                __half2 lp1 = {__float2half_rn(v2 - __half2float(h2)),
                               __float2half_rn(v3 - __half2float(h3))};
                *(uint32_t*)(Ch + (size_t)row0 * N + col)       = *(uint32_t*)&hp0;
                *(uint32_t*)(Ch + (size_t)(row0 + 8) * N + col) = *(uint32_t*)&hp1;
                *(uint32_t*)(Cl + (size_t)row0 * N + col)       = *(uint32_t*)&lp0;
                *(uint32_t*)(Cl + (size_t)(row0 + 8) * N + col) = *(uint32_t*)&lp1;
            } else {
                *(float2*)(C + (size_t)row0 * N + col)       = make_float2(v0, v1);
                *(float2*)(C + (size_t)(row0 + 8) * N + col) = make_float2(v2, v3);
            }
        }
    }
}

// ---------------- fp32 -> fp16 hi/lo split (activations) ----------------
__global__ void split_kernel(const float* __restrict__ in,
                             __half* __restrict__ hi,
                             __half* __restrict__ lo, int n4)
{
    int i = blockIdx.x * blockDim.x + threadIdx.x;
    if (i >= n4) return;
    float4 v = ((const float4*)in)[i];
    __align__(8) __half h[4], l[4];
    #pragma unroll
    for (int j = 0; j < 4; j++) {
        float x = (&v.x)[j];
        __half hh = __float2half_rn(x);
        h[j] = hh;
        l[j] = __float2half_rn(x - __half2float(hh));
    }
    ((uint2*)hi)[i] = *(const uint2*)h;
    ((uint2*)lo)[i] = *(const uint2*)l;
}

// ---------------- fp32 -> fp16 convert (weights, single plane) ----------------
__global__ void convert_kernel(const float* __restrict__ in,
                               __half* __restrict__ out, int n4)
{
    int i = blockIdx.x * blockDim.x + threadIdx.x;
    if (i >= n4) return;
    float4 v = ((const float4*)in)[i];
    __align__(8) __half h[4];
    #pragma unroll
    for (int j = 0; j < 4; j++) h[j] = __float2half_rn((&v.x)[j]);
    ((uint2*)out)[i] = *(const uint2*)h;
}

// ---------------- fused LayerNorm + fp16 split ----------------
__global__ void ln_split_kernel(const float* __restrict__ x,
                                const float* __restrict__ g,
                                const float* __restrict__ b,
                                __half* __restrict__ hi,
                                __half* __restrict__ lo)
{
    __shared__ float red[16];
    const int row = blockIdx.x;
    const int i0 = threadIdx.x * 4;
    const float* xr = x + (size_t)row * D_;
    float4 v = *(const float4*)(xr + i0);
    float s  = v.x + v.y + v.z + v.w;
    float sq = v.x*v.x + v.y*v.y + v.z*v.z + v.w*v.w;
    #pragma unroll
    for (int o = 16; o >= 1; o >>= 1) {
        s  += __shfl_xor_sync(0xffffffffu, s,  o);
        sq += __shfl_xor_sync(0xffffffffu, sq, o);
    }
    int w = threadIdx.x >> 5, lane = threadIdx.x & 31;
    if (lane == 0) { red[w] = s; red[w + 8] = sq; }
    __syncthreads();
    if (threadIdx.x == 0) {
        float ts = 0.f, tq = 0.f;
        #pragma unroll
        for (int i = 0; i < 8; i++) { ts += red[i]; tq += red[i + 8]; }
        float mean = ts * (1.0f / D_);
        float var  = tq * (1.0f / D_) - mean * mean;
        red[0] = mean;
        red[1] = rsqrtf(var + LN_EPS);
    }
    __syncthreads();
    float mean = red[0], rstd = red[1];
    float4 gv = *(const float4*)(g + i0);
    float4 bv = *(const float4*)(b + i0);
    __align__(8) __half h[4], l[4];
    #pragma unroll
    for (int j = 0; j < 4; j++) {
        float y = ((&v.x)[j] - mean) * rstd * (&gv.x)[j] + (&bv.x)[j];
        __half hh = __float2half_rn(y);
        h[j] = hh;
        l[j] = __float2half_rn(y - __half2float(hh));
    }
    *(uint2*)(hi + (size_t)row * D_ + i0) = *(const uint2*)h;
    *(uint2*)(lo + (size_t)row * D_ + i0) = *(const uint2*)l;
}

// ---------------- LoRA down (reads fp16 hi/lo activation) ----------------
__global__ void lora_down_kernel(const __half* __restrict__ AH,
                                 const __half* __restrict__ AL,
                                 const float* __restrict__ la1,
                                 const float* __restrict__ la2,
                                 float* __restrict__ t1,
                                 float* __restrict__ t2)
{
    __shared__ float hs[D_];
    const int row = blockIdx.x;
    for (int i = threadIdx.x; i < D_; i += 256)
        hs[i] = __half2float(AH[(size_t)row * D_ + i]) +
                __half2float(AL[(size_t)row * D_ + i]);
    __syncthreads();
    int w = threadIdx.x >> 5, lane = threadIdx.x & 31;
    const float* la; float* t; int r;
    if (w < 4) { la = la1; t = t1; r = w; }
    else       { la = la2; t = t2; r = w - 4; }
    if (la == nullptr) return;
    const float* lar = la + r * D_;
    float s = 0.f;
    for (int i = lane; i < D_; i += 32) s += hs[i] * lar[i];
    #pragma unroll
    for (int o = 16; o >= 1; o >>= 1) s += __shfl_xor_sync(0xffffffffu, s, o);
    if (lane == 0) t[row * 4 + r] = s;
}

// ---------------- flash attention (measured-passing, fp16 split output) ------
#define QPAD 68
#define PPAD 36
__global__ void __launch_bounds__(256)
attn_kernel(const float* __restrict__ Q, const float* __restrict__ K,
            const float* __restrict__ V,
            __half* __restrict__ CH, __half* __restrict__ CL)
{
    __shared__ float Qs[64 * QPAD];
    __shared__ float Ks[32 * QPAD];
    __shared__ float Vs[32 * QPAD];
    __shared__ float Ps[64 * PPAD];

    const int qt = blockIdx.x & 15;
    const int h  = (blockIdx.x >> 4) & 15;
    const int b  = blockIdx.x >> 8;
    const int tid = threadIdx.x;
    const int ty = tid >> 4, tx = tid & 15;

    const size_t headoff = (size_t)h * HD_;
    const float* qg = Q + ((size_t)(b * S_ + qt * 64)) * D_ + headoff;

    for (int idx = tid; idx < 64 * 64; idx += 256) {
        int r = idx >> 6, c = idx & 63;
        Qs[r * QPAD + c] = qg[(size_t)r * D_ + c] * 0.125f;
    }

    float m[4], l[4], o_acc[4][4];
    #pragma unroll
    for (int i = 0; i < 4; i++) {
        m[i] = -1e30f; l[i] = 0.f;
        #pragma unroll
        for (int j = 0; j < 4; j++) o_acc[i][j] = 0.f;
    }

    for (int kt = 0; kt < S_ / 32; kt++) {
        __syncthreads();
        const float* kg = K + ((size_t)(b * S_ + kt * 32)) * D_ + headoff;
        const float* vg = V + ((size_t)(b * S_ + kt * 32)) * D_ + headoff;
        for (int idx = tid; idx < 32 * 64; idx += 256) {
            int r = idx >> 6, c = idx & 63;
            Ks[r * QPAD + c] = kg[(size_t)r * D_ + c];
            Vs[r * QPAD + c] = vg[(size_t)r * D_ + c];
        }
        __syncthreads();

        float sc[4][2] = {{0.f,0.f},{0.f,0.f},{0.f,0.f},{0.f,0.f}};
        #pragma unroll
        for (int k4 = 0; k4 < 16; k4++) {
            float4 kv0 = *(const float4*)&Ks[(tx * 2 + 0) * QPAD + k4 * 4];
            float4 kv1 = *(const float4*)&Ks[(tx * 2 + 1) * QPAD + k4 * 4];
            #pragma unroll
            for (int i = 0; i < 4; i++) {
                float4 qv = *(const float4*)&Qs[(ty * 4 + i) * QPAD + k4 * 4];
                sc[i][0] += qv.x * kv0.x + qv.y * kv0.y + qv.z * kv0.z + qv.w * kv0.w;
                sc[i][1] += qv.x * kv1.x + qv.y * kv1.y + qv.z * kv1.z + qv.w * kv1.w;
            }
        }

        #pragma unroll
        for (int i = 0; i < 4; i++) {
            float mx = fmaxf(sc[i][0], sc[i][1]);
            #pragma unroll
            for (int o = 8; o >= 1; o >>= 1)
                mx = fmaxf(mx, __shfl_xor_sync(0xffffffffu, mx, o, 16));
            float mnew = fmaxf(m[i], mx);
            float corr = __expf(m[i] - mnew);
            float p0 = __expf(sc[i][0] - mnew);
            float p1 = __expf(sc[i][1] - mnew);
            float rs = p0 + p1;
            #pragma unroll
            for (int o = 8; o >= 1; o >>= 1)
                rs += __shfl_xor_sync(0xffffffffu, rs, o, 16);
            m[i] = mnew;
            l[i] = l[i] * corr + rs;
            #pragma unroll
            for (int j = 0; j < 4; j++) o_acc[i][j] *= corr;
            Ps[(ty * 4 + i) * PPAD + tx * 2 + 0] = p0;
            Ps[(ty * 4 + i) * PPAD + tx * 2 + 1] = p1;
        }
        __syncthreads();

        #pragma unroll
        for (int kk = 0; kk < 32; kk++) {
            float4 vv = *(const float4*)&Vs[kk * QPAD + tx * 4];
            #pragma unroll
            for (int i = 0; i < 4; i++) {
                float p = Ps[(ty * 4 + i) * PPAD + kk];
                o_acc[i][0] += p * vv.x;
                o_acc[i][1] += p * vv.y;
                o_acc[i][2] += p * vv.z;
                o_acc[i][3] += p * vv.w;
            }
        }
    }

    const size_t obase = ((size_t)(b * S_ + qt * 64)) * D_ + headoff;
    #pragma unroll
    for (int i = 0; i < 4; i++) {
        float inv = 1.0f / l[i];
        __align__(8) __half hb[4], lbv[4];
        #pragma unroll
        for (int j = 0; j < 4; j++) {
            float v = o_acc[i][j] * inv;
            __half hh = __float2half_rn(v);
            hb[j] = hh;
            lbv[j] = __float2half_rn(v - __half2float(hh));
        }
        const size_t off = obase + (size_t)(ty * 4 + i) * D_ + tx * 4;
        *(uint2*)(CH + off) = *(const uint2*)hb;
        *(uint2*)(CL + off) = *(const uint2*)lbv;
    }
}

// ---------------- host launch ----------------
extern "C" void kernel_launch(void* const* d_in, const int* in_sizes, int n_in,
                              void* d_out, int out_size)
{
    const float* x      = (const float*)d_in[0];
    const float* Wq     = (const float*)d_in[1];
    const float* bq     = (const float*)d_in[2];
    const float* Wk     = (const float*)d_in[3];
    const float* Wv     = (const float*)d_in[4];
    const float* bv     = (const float*)d_in[5];
    const float* Wo     = (const float*)d_in[6];
    const float* bo     = (const float*)d_in[7];
    const float* la_k   = (const float*)d_in[8];
    const float* lb_k   = (const float*)d_in[9];
    const float* la_v   = (const float*)d_in[10];
    const float* lb_v   = (const float*)d_in[11];
    const float* la_o   = (const float*)d_in[12];
    const float* lb_o   = (const float*)d_in[13];
    const float* g_attn = (const float*)d_in[14];
    const float* b_attn = (const float*)d_in[15];
    const float* W1     = (const float*)d_in[16];
    const float* b1     = (const float*)d_in[17];
    const float* W2     = (const float*)d_in[18];
    const float* b2     = (const float*)d_in[19];
    const float* g_mlp  = (const float*)d_in[20];
    const float* b_mlp  = (const float*)d_in[21];
    float* out = (float*)d_out;

    float *Qf, *Kf, *Vf, *X1, *TK, *TV, *TO;
    __half *AH, *AL, *UH, *UL, *WH;
    cudaGetSymbolAddress((void**)&Qf,  g_qf);
    cudaGetSymbolAddress((void**)&Kf,  g_kf);
    cudaGetSymbolAddress((void**)&Vf,  g_vf);
    cudaGetSymbolAddress((void**)&X1,  g_x1);
    cudaGetSymbolAddress((void**)&TK,  g_tk);
    cudaGetSymbolAddress((void**)&TV,  g_tv);
    cudaGetSymbolAddress((void**)&TO,  g_to);
    cudaGetSymbolAddress((void**)&AH,  g_ah);
    cudaGetSymbolAddress((void**)&AL,  g_al);
    cudaGetSymbolAddress((void**)&UH,  g_uh);
    cudaGetSymbolAddress((void**)&UL,  g_ul);
    cudaGetSymbolAddress((void**)&WH,  g_wh);

    cudaFuncSetAttribute(gemm_tc<0>, cudaFuncAttributeMaxDynamicSharedMemorySize, GEMM_SMEM);
    cudaFuncSetAttribute(gemm_tc<1>, cudaFuncAttributeMaxDynamicSharedMemorySize, GEMM_SMEM);
    cudaFuncSetAttribute(gemm_tc<2>, cudaFuncAttributeMaxDynamicSharedMemorySize, GEMM_SMEM);
    cudaFuncSetAttribute(gemm_tc<3>, cudaFuncAttributeMaxDynamicSharedMemorySize, GEMM_SMEM);
    cudaFuncSetAttribute(gemm_tc<4>, cudaFuncAttributeMaxDynamicSharedMemorySize, GEMM_SMEM);

    const int MM = 1024 * 1024;
    // weight offsets (elements): Wq 0, Wk 1M, Wv 2M, Wo 3M, W1 4M, W2 8M
    convert_kernel<<<(MM / 4 + 255) / 256, 256>>>(Wq, WH + 0 * MM, MM / 4);
    convert_kernel<<<(MM / 4 + 255) / 256, 256>>>(Wk, WH + 1 * MM, MM / 4);
    convert_kernel<<<(MM / 4 + 255) / 256, 256>>>(Wv, WH + 2 * MM, MM / 4);
    convert_kernel<<<(MM / 4 + 255) / 256, 256>>>(Wo, WH + 3 * MM, MM / 4);
    convert_kernel<<<(MM + 255) / 256, 256>>>(W1, WH + 4 * MM, MM);
    convert_kernel<<<(MM + 255) / 256, 256>>>(W2, WH + 8 * MM, MM);

    const dim3 gD(D_ / 128, M_ / 128);
    const dim3 gF(DFF_ / 128, M_ / 128);

    // 1. LN1 -> fp16 split
    ln_split_kernel<<<M_, 256>>>(x, g_attn, b_attn, AH, AL);
    // 2. LoRA down for k, v
    lora_down_kernel<<<M_, 256>>>(AH, AL, la_k, la_v, TK, TV);
    // 3-5. Q/K/V projections (rank4 fused for K, V)
    gemm_tc<0><<<gD, 256, GEMM_SMEM>>>(AH, AL, WH + 0 * MM, bq,      Qf, nullptr, nullptr, nullptr, nullptr, nullptr, M_, D_, D_);
    gemm_tc<2><<<gD, 256, GEMM_SMEM>>>(AH, AL, WH + 1 * MM, nullptr, Kf, nullptr, nullptr, nullptr, TK, lb_k, M_, D_, D_);
    gemm_tc<2><<<gD, 256, GEMM_SMEM>>>(AH, AL, WH + 2 * MM, bv,      Vf, nullptr, nullptr, nullptr, TV, lb_v, M_, D_, D_);
    // 6. attention -> ctx fp16 split (overwrites AH/AL)
    attn_kernel<<<B_ * NH_ * (S_ / 64), 256>>>(Qf, Kf, Vf, AH, AL);
    // 7. LoRA down for o
    lora_down_kernel<<<M_, 256>>>(AH, AL, la_o, nullptr, TO, nullptr);
    // 8. O projection: X1 = x + ctx@Wo^T + bo + lora_o
    gemm_tc<3><<<gD, 256, GEMM_SMEM>>>(AH, AL, WH + 3 * MM, bo, X1, nullptr, nullptr, x, TO, lb_o, M_, D_, D_);
    // 9. LN2 -> fp16 split
    ln_split_kernel<<<M_, 256>>>(X1, g_mlp, b_mlp, AH, AL);
    // 10. MLP1: gelu -> fp16 split
    gemm_tc<1><<<gF, 256, GEMM_SMEM>>>(AH, AL, WH + 4 * MM, b1, nullptr, UH, UL, nullptr, nullptr, nullptr, M_, DFF_, D_);
    // 11. MLP2: out = X1 + U@W2^T + b2
    gemm_tc<4><<<gD, 256, GEMM_SMEM>>>(UH, UL, WH + 8 * MM, b2, out, nullptr, nullptr, X1, nullptr, nullptr, M_, D_, DFF_);
}

// round 17
// speedup vs baseline: 1.5524x; 1.2421x over previous
#include <cuda_runtime.h>
#include <cuda_fp16.h>
#include <cmath>
#include <cstdint>

// ---------------- problem constants ----------------
#define B_   8
#define S_   1024
#define D_   1024
#define NH_  16
#define HD_  64
#define M_   (B_ * S_)          // 8192 rows
#define DFF_ (4 * D_)           // 4096
#define LN_EPS 1e-5f
#define LORA_SCALE 0.25f

// ---------------- scratch (device globals) -----------
__device__ float g_qf [M_ * D_];
__device__ float g_kf [M_ * D_];
__device__ float g_vf [M_ * D_];
__device__ float g_x1 [M_ * D_];
__device__ float g_tk [M_ * 4];
__device__ float g_tv [M_ * 4];
__device__ float g_to [M_ * 4];
__device__ __half g_ah[M_ * D_];      // activation (fp16, single plane)
__device__ __half g_uh[M_ * DFF_];    // MLP hidden (fp16)
__device__ __half g_wh[12 * 1024 * 1024];  // weights fp16 (Wq,Wk,Wv,Wo,W1,W2)

// ================= helpers =================
__device__ __forceinline__ uint32_t smem_to_u32(const void* p) {
    uint32_t a;
    asm("{ .reg .u64 t; cvta.to.shared.u64 t, %1; cvt.u32.u64 %0, t; }" : "=r"(a) : "l"(p));
    return a;
}
__device__ __forceinline__ void cp_async16(uint32_t dst, const void* src) {
    asm volatile("cp.async.cg.shared.global [%0], [%1], 16;" :: "r"(dst), "l"(src));
}
#define CP_COMMIT()  asm volatile("cp.async.commit_group;" ::: "memory")
#define CP_WAIT0()   asm volatile("cp.async.wait_group 0;" ::: "memory")
#define CP_WAIT1()   asm volatile("cp.async.wait_group 1;" ::: "memory")

#define MMA_F16(d, a, b)                                                       \
    asm volatile(                                                              \
        "mma.sync.aligned.m16n8k16.row.col.f32.f16.f16.f32 "                   \
        "{%0,%1,%2,%3}, {%4,%5,%6,%7}, {%8,%9}, {%0,%1,%2,%3};"                \
        : "+f"((d)[0]), "+f"((d)[1]), "+f"((d)[2]), "+f"((d)[3])               \
        : "r"((a)[0]), "r"((a)[1]), "r"((a)[2]), "r"((a)[3]),                  \
          "r"((b)[0]), "r"((b)[1]))

// ================= mma.sync GEMM (1-pass fp16) =================
// C = A @ B^T, both fp16 (each 2^-11). Pipeline/occ identical to measured
// 2773us kernel; Al plane dropped -> half the MMA work, 2 tiles/chunk.
// EPI: 0 = fp32 +bias | 1 = gelu->fp16 | 2 = +bias? +rank4 |
//      3 = resid + bias + rank4 | 4 = resid + bias
#define SROW 40                       // halves per smem row (80B)
#define TILE_B (128 * SROW * 2)       // 10240 bytes
#define STAGE_B (2 * TILE_B)          // Ah, Bh
#define GEMM_SMEM (2 * STAGE_B)       // 40960

template<int EPI>
__global__ void __launch_bounds__(256, 2)
gemm_tc(const __half* __restrict__ Ah, const __half* __restrict__ Bh,
        const float* __restrict__ bias, float* __restrict__ C,
        __half* __restrict__ Ch,
        const float* __restrict__ resid, const float* __restrict__ t4,
        const float* __restrict__ lb,
        int M, int N, int K)
{
    extern __shared__ char sm[];
    const uint32_t smem_u32 = smem_to_u32(sm);
    const int tid  = threadIdx.x;
    const int lane = tid & 31;
    const int g    = lane >> 2, tg = lane & 3;
    const int w    = tid >> 5;
    const int wm   = w >> 2;          // 0..1
    const int wn   = w & 3;           // 0..3
    const int bm   = blockIdx.y * 128, bn = blockIdx.x * 128;

    const size_t rowb = (size_t)K * 2;
    const char* srcA_h = (const char*)(Ah + (size_t)bm * K);
    const char* srcB_h = (const char*)(Bh + (size_t)bn * K);

    const int NC = K >> 5;                 // K / 32

    auto load_chunk = [&](int c, int s) {
        const uint32_t sb = smem_u32 + s * STAGE_B;
        const size_t coff = (size_t)c * 64;
        #pragma unroll
        for (int t = 0; t < 2; t++) {
            const int unit = tid + t * 256;
            const int row = unit >> 2, cb = unit & 3;
            const size_t so = (size_t)row * rowb + coff + cb * 16;
            const uint32_t doff = row * 80 + cb * 16;
            cp_async16(sb + 0 * TILE_B + doff, srcA_h + so);
            cp_async16(sb + 1 * TILE_B + doff, srcB_h + so);
        }
        CP_COMMIT();
    };

    float acc[4][4][4];
    #pragma unroll
    for (int mi = 0; mi < 4; mi++)
        #pragma unroll
        for (int ni = 0; ni < 4; ni++)
            #pragma unroll
            for (int q = 0; q < 4; q++) acc[mi][ni][q] = 0.f;

    load_chunk(0, 0);

    for (int c = 0; c < NC; c++) {
        const int s = c & 1;
        if (c + 1 < NC) { load_chunk(c + 1, (c + 1) & 1); CP_WAIT1(); }
        else            { CP_WAIT0(); }
        __syncthreads();

        const __half* sA_h = (const __half*)(sm + s * STAGE_B + 0 * TILE_B);
        const __half* sB_h = (const __half*)(sm + s * STAGE_B + 1 * TILE_B);

        #pragma unroll
        for (int ks = 0; ks < 2; ks++) {
            const int kc = ks * 16 + 2 * tg;
            uint32_t bh[4][2];
            #pragma unroll
            for (int ni = 0; ni < 4; ni++) {
                const int n = wn * 32 + ni * 8 + g;
                bh[ni][0] = *(const uint32_t*)(sB_h + n * SROW + kc);
                bh[ni][1] = *(const uint32_t*)(sB_h + n * SROW + kc + 8);
            }
            #pragma unroll
            for (int mi = 0; mi < 4; mi++) {
                const int r0 = wm * 64 + mi * 16 + g;
                uint32_t ah[4];
                ah[0] = *(const uint32_t*)(sA_h + r0 * SROW + kc);
                ah[1] = *(const uint32_t*)(sA_h + (r0 + 8) * SROW + kc);
                ah[2] = *(const uint32_t*)(sA_h + r0 * SROW + kc + 8);
                ah[3] = *(const uint32_t*)(sA_h + (r0 + 8) * SROW + kc + 8);
                #pragma unroll
                for (int ni = 0; ni < 4; ni++)
                    MMA_F16(acc[mi][ni], ah, bh[ni]);
            }
        }
        __syncthreads();
    }

    // ---- fused epilogue ----
    #pragma unroll
    for (int mi = 0; mi < 4; mi++) {
        const int row0 = bm + wm * 64 + mi * 16 + g;
        float4 tr0, tr1;
        if (EPI == 2 || EPI == 3) {
            tr0 = *(const float4*)(t4 + (size_t)row0 * 4);
            tr1 = *(const float4*)(t4 + (size_t)(row0 + 8) * 4);
        }
        #pragma unroll
        for (int ni = 0; ni < 4; ni++) {
            const int col = bn + wn * 32 + ni * 8 + 2 * tg;
            const float bx = bias ? bias[col]     : 0.f;
            const float by = bias ? bias[col + 1] : 0.f;
            float v0 = acc[mi][ni][0] + bx, v1 = acc[mi][ni][1] + by;
            float v2 = acc[mi][ni][2] + bx, v3 = acc[mi][ni][3] + by;
            if (EPI == 2 || EPI == 3) {
                float4 c0 = *(const float4*)(lb + (size_t)col * 4);
                float4 c1 = *(const float4*)(lb + (size_t)(col + 1) * 4);
                v0 += LORA_SCALE * (tr0.x*c0.x + tr0.y*c0.y + tr0.z*c0.z + tr0.w*c0.w);
                v1 += LORA_SCALE * (tr0.x*c1.x + tr0.y*c1.y + tr0.z*c1.z + tr0.w*c1.w);
                v2 += LORA_SCALE * (tr1.x*c0.x + tr1.y*c0.y + tr1.z*c0.z + tr1.w*c0.w);
                v3 += LORA_SCALE * (tr1.x*c1.x + tr1.y*c1.y + tr1.z*c1.z + tr1.w*c1.w);
            }
            if (EPI == 3 || EPI == 4) {
                v0 += resid[(size_t)row0 * N + col];
                v1 += resid[(size_t)row0 * N + col + 1];
                v2 += resid[(size_t)(row0 + 8) * N + col];
                v3 += resid[(size_t)(row0 + 8) * N + col + 1];
            }
            if (EPI == 1) {
                v0 = 0.5f * v0 * (1.0f + erff(v0 * 0.70710678118654752f));
                v1 = 0.5f * v1 * (1.0f + erff(v1 * 0.70710678118654752f));
                v2 = 0.5f * v2 * (1.0f + erff(v2 * 0.70710678118654752f));
                v3 = 0.5f * v3 * (1.0f + erff(v3 * 0.70710678118654752f));
                __half2 hp0 = {__float2half_rn(v0), __float2half_rn(v1)};
                __half2 hp1 = {__float2half_rn(v2), __float2half_rn(v3)};
                *(uint32_t*)(Ch + (size_t)row0 * N + col)       = *(uint32_t*)&hp0;
                *(uint32_t*)(Ch + (size_t)(row0 + 8) * N + col) = *(uint32_t*)&hp1;
            } else {
                *(float2*)(C + (size_t)row0 * N + col)       = make_float2(v0, v1);
                *(float2*)(C + (size_t)(row0 + 8) * N + col) = make_float2(v2, v3);
            }
        }
    }
}

// ---------------- fp32 -> fp16 convert ----------------
__global__ void convert_kernel(const float* __restrict__ in,
                               __half* __restrict__ out, int n4)
{
    int i = blockIdx.x * blockDim.x + threadIdx.x;
    if (i >= n4) return;
    float4 v = ((const float4*)in)[i];
    __align__(8) __half h[4];
    #pragma unroll
    for (int j = 0; j < 4; j++) h[j] = __float2half_rn((&v.x)[j]);
    ((uint2*)out)[i] = *(const uint2*)h;
}

// ---------------- fused LayerNorm -> fp16 ----------------
__global__ void ln_fp16_kernel(const float* __restrict__ x,
                               const float* __restrict__ g,
                               const float* __restrict__ b,
                               __half* __restrict__ out)
{
    __shared__ float red[16];
    const int row = blockIdx.x;
    const int i0 = threadIdx.x * 4;
    const float* xr = x + (size_t)row * D_;
    float4 v = *(const float4*)(xr + i0);
    float s  = v.x + v.y + v.z + v.w;
    float sq = v.x*v.x + v.y*v.y + v.z*v.z + v.w*v.w;
    #pragma unroll
    for (int o = 16; o >= 1; o >>= 1) {
        s  += __shfl_xor_sync(0xffffffffu, s,  o);
        sq += __shfl_xor_sync(0xffffffffu, sq, o);
    }
    int w = threadIdx.x >> 5, lane = threadIdx.x & 31;
    if (lane == 0) { red[w] = s; red[w + 8] = sq; }
    __syncthreads();
    if (threadIdx.x == 0) {
        float ts = 0.f, tq = 0.f;
        #pragma unroll
        for (int i = 0; i < 8; i++) { ts += red[i]; tq += red[i + 8]; }
        float mean = ts * (1.0f / D_);
        float var  = tq * (1.0f / D_) - mean * mean;
        red[0] = mean;
        red[1] = rsqrtf(var + LN_EPS);
    }
    __syncthreads();
    float mean = red[0], rstd = red[1];
    float4 gv = *(const float4*)(g + i0);
    float4 bv = *(const float4*)(b + i0);
    __align__(8) __half h[4];
    #pragma unroll
    for (int j = 0; j < 4; j++) {
        float y = ((&v.x)[j] - mean) * rstd * (&gv.x)[j] + (&bv.x)[j];
        h[j] = __float2half_rn(y);
    }
    *(uint2*)(out + (size_t)row * D_ + i0) = *(const uint2*)h;
}

// ---------------- LoRA down (reads fp16 activation) ----------------
__global__ void lora_down_kernel(const __half* __restrict__ A,
                                 const float* __restrict__ la1,
                                 const float* __restrict__ la2,
                                 float* __restrict__ t1,
                                 float* __restrict__ t2)
{
    __shared__ float hs[D_];
    const int row = blockIdx.x;
    for (int i = threadIdx.x; i < D_; i += 256)
        hs[i] = __half2float(A[(size_t)row * D_ + i]);
    __syncthreads();
    int w = threadIdx.x >> 5, lane = threadIdx.x & 31;
    const float* la; float* t; int r;
    if (w < 4) { la = la1; t = t1; r = w; }
    else       { la = la2; t = t2; r = w - 4; }
    if (la == nullptr) return;
    const float* lar = la + r * D_;
    float s = 0.f;
    for (int i = lane; i < D_; i += 32) s += hs[i] * lar[i];
    #pragma unroll
    for (int o = 16; o >= 1; o >>= 1) s += __shfl_xor_sync(0xffffffffu, s, o);
    if (lane == 0) t[row * 4 + r] = s;
}

// ---------------- flash attention (measured-passing, fp16 ctx output) --------
#define QPAD 68
#define PPAD 36
__global__ void __launch_bounds__(256)
attn_kernel(const float* __restrict__ Q, const float* __restrict__ K,
            const float* __restrict__ V, __half* __restrict__ CH)
{
    __shared__ float Qs[64 * QPAD];
    __shared__ float Ks[32 * QPAD];
    __shared__ float Vs[32 * QPAD];
    __shared__ float Ps[64 * PPAD];

    const int qt = blockIdx.x & 15;
    const int h  = (blockIdx.x >> 4) & 15;
    const int b  = blockIdx.x >> 8;
    const int tid = threadIdx.x;
    const int ty = tid >> 4, tx = tid & 15;

    const size_t headoff = (size_t)h * HD_;
    const float* qg = Q + ((size_t)(b * S_ + qt * 64)) * D_ + headoff;

    for (int idx = tid; idx < 64 * 64; idx += 256) {
        int r = idx >> 6, c = idx & 63;
        Qs[r * QPAD + c] = qg[(size_t)r * D_ + c] * 0.125f;
    }

    float m[4], l[4], o_acc[4][4];
    #pragma unroll
    for (int i = 0; i < 4; i++) {
        m[i] = -1e30f; l[i] = 0.f;
        #pragma unroll
        for (int j = 0; j < 4; j++) o_acc[i][j] = 0.f;
    }

    for (int kt = 0; kt < S_ / 32; kt++) {
        __syncthreads();
        const float* kg = K + ((size_t)(b * S_ + kt * 32)) * D_ + headoff;
        const float* vg = V + ((size_t)(b * S_ + kt * 32)) * D_ + headoff;
        for (int idx = tid; idx < 32 * 64; idx += 256) {
            int r = idx >> 6, c = idx & 63;
            Ks[r * QPAD + c] = kg[(size_t)r * D_ + c];
            Vs[r * QPAD + c] = vg[(size_t)r * D_ + c];
        }
        __syncthreads();

        float sc[4][2] = {{0.f,0.f},{0.f,0.f},{0.f,0.f},{0.f,0.f}};
        #pragma unroll
        for (int k4 = 0; k4 < 16; k4++) {
            float4 kv0 = *(const float4*)&Ks[(tx * 2 + 0) * QPAD + k4 * 4];
            float4 kv1 = *(const float4*)&Ks[(tx * 2 + 1) * QPAD + k4 * 4];
            #pragma unroll
            for (int i = 0; i < 4; i++) {
                float4 qv = *(const float4*)&Qs[(ty * 4 + i) * QPAD + k4 * 4];
                sc[i][0] += qv.x * kv0.x + qv.y * kv0.y + qv.z * kv0.z + qv.w * kv0.w;
                sc[i][1] += qv.x * kv1.x + qv.y * kv1.y + qv.z * kv1.z + qv.w * kv1.w;
            }
        }

        #pragma unroll
        for (int i = 0; i < 4; i++) {
            float mx = fmaxf(sc[i][0], sc[i][1]);
            #pragma unroll
            for (int o = 8; o >= 1; o >>= 1)
                mx = fmaxf(mx, __shfl_xor_sync(0xffffffffu, mx, o, 16));
            float mnew = fmaxf(m[i], mx);
            float corr = __expf(m[i] - mnew);
            float p0 = __expf(sc[i][0] - mnew);
            float p1 = __expf(sc[i][1] - mnew);
            float rs = p0 + p1;
            #pragma unroll
            for (int o = 8; o >= 1; o >>= 1)
                rs += __shfl_xor_sync(0xffffffffu, rs, o, 16);
            m[i] = mnew;
            l[i] = l[i] * corr + rs;
            #pragma unroll
            for (int j = 0; j < 4; j++) o_acc[i][j] *= corr;
            Ps[(ty * 4 + i) * PPAD + tx * 2 + 0] = p0;
            Ps[(ty * 4 + i) * PPAD + tx * 2 + 1] = p1;
        }
        __syncthreads();

        #pragma unroll
        for (int kk = 0; kk < 32; kk++) {
            float4 vv = *(const float4*)&Vs[kk * QPAD + tx * 4];
            #pragma unroll
            for (int i = 0; i < 4; i++) {
                float p = Ps[(ty * 4 + i) * PPAD + kk];
                o_acc[i][0] += p * vv.x;
                o_acc[i][1] += p * vv.y;
                o_acc[i][2] += p * vv.z;
                o_acc[i][3] += p * vv.w;
            }
        }
    }

    const size_t obase = ((size_t)(b * S_ + qt * 64)) * D_ + headoff;
    #pragma unroll
    for (int i = 0; i < 4; i++) {
        float inv = 1.0f / l[i];
        __align__(8) __half hb[4];
        #pragma unroll
        for (int j = 0; j < 4; j++)
            hb[j] = __float2half_rn(o_acc[i][j] * inv);
        const size_t off = obase + (size_t)(ty * 4 + i) * D_ + tx * 4;
        *(uint2*)(CH + off) = *(const uint2*)hb;
    }
}

// ---------------- host launch ----------------
extern "C" void kernel_launch(void* const* d_in, const int* in_sizes, int n_in,
                              void* d_out, int out_size)
{
    const float* x      = (const float*)d_in[0];
    const float* Wq     = (const float*)d_in[1];
    const float* bq     = (const float*)d_in[2];
    const float* Wk     = (const float*)d_in[3];
    const float* Wv     = (const float*)d_in[4];
    const float* bv     = (const float*)d_in[5];
    const float* Wo     = (const float*)d_in[6];
    const float* bo     = (const float*)d_in[7];
    const float* la_k   = (const float*)d_in[8];
    const float* lb_k   = (const float*)d_in[9];
    const float* la_v   = (const float*)d_in[10];
    const float* lb_v   = (const float*)d_in[11];
    const float* la_o   = (const float*)d_in[12];
    const float* lb_o   = (const float*)d_in[13];
    const float* g_attn = (const float*)d_in[14];
    const float* b_attn = (const float*)d_in[15];
    const float* W1     = (const float*)d_in[16];
    const float* b1     = (const float*)d_in[17];
    const float* W2     = (const float*)d_in[18];
    const float* b2     = (const float*)d_in[19];
    const float* g_mlp  = (const float*)d_in[20];
    const float* b_mlp  = (const float*)d_in[21];
    float* out = (float*)d_out;

    float *Qf, *Kf, *Vf, *X1, *TK, *TV, *TO;
    __half *AH, *UH, *WH;
    cudaGetSymbolAddress((void**)&Qf,  g_qf);
    cudaGetSymbolAddress((void**)&Kf,  g_kf);
    cudaGetSymbolAddress((void**)&Vf,  g_vf);
    cudaGetSymbolAddress((void**)&X1,  g_x1);
    cudaGetSymbolAddress((void**)&TK,  g_tk);
    cudaGetSymbolAddress((void**)&TV,  g_tv);
    cudaGetSymbolAddress((void**)&TO,  g_to);
    cudaGetSymbolAddress((void**)&AH,  g_ah);
    cudaGetSymbolAddress((void**)&UH,  g_uh);
    cudaGetSymbolAddress((void**)&WH,  g_wh);

    cudaFuncSetAttribute(gemm_tc<0>, cudaFuncAttributeMaxDynamicSharedMemorySize, GEMM_SMEM);
    cudaFuncSetAttribute(gemm_tc<1>, cudaFuncAttributeMaxDynamicSharedMemorySize, GEMM_SMEM);
    cudaFuncSetAttribute(gemm_tc<2>, cudaFuncAttributeMaxDynamicSharedMemorySize, GEMM_SMEM);
    cudaFuncSetAttribute(gemm_tc<3>, cudaFuncAttributeMaxDynamicSharedMemorySize, GEMM_SMEM);
    cudaFuncSetAttribute(gemm_tc<4>, cudaFuncAttributeMaxDynamicSharedMemorySize, GEMM_SMEM);

    const int MM = 1024 * 1024;
    // weight offsets (elements): Wq 0, Wk 1M, Wv 2M, Wo 3M, W1 4M, W2 8M
    convert_kernel<<<(MM / 4 + 255) / 256, 256>>>(Wq, WH + 0 * MM, MM / 4);
    convert_kernel<<<(MM / 4 + 255) / 256, 256>>>(Wk, WH + 1 * MM, MM / 4);
    convert_kernel<<<(MM / 4 + 255) / 256, 256>>>(Wv, WH + 2 * MM, MM / 4);
    convert_kernel<<<(MM / 4 + 255) / 256, 256>>>(Wo, WH + 3 * MM, MM / 4);
    convert_kernel<<<(MM + 255) / 256, 256>>>(W1, WH + 4 * MM, MM);
    convert_kernel<<<(MM + 255) / 256, 256>>>(W2, WH + 8 * MM, MM);

    const dim3 gD(D_ / 128, M_ / 128);
    const dim3 gF(DFF_ / 128, M_ / 128);

    // 1. LN1 -> fp16
    ln_fp16_kernel<<<M_, 256>>>(x, g_attn, b_attn, AH);
    // 2. LoRA down for k, v
    lora_down_kernel<<<M_, 256>>>(AH, la_k, la_v, TK, TV);
    // 3-5. Q/K/V projections (rank4 fused for K, V)
    gemm_tc<0><<<gD, 256, GEMM_SMEM>>>(AH, WH + 0 * MM, bq,      Qf, nullptr, nullptr, nullptr, nullptr, M_, D_, D_);
    gemm_tc<2><<<gD, 256, GEMM_SMEM>>>(AH, WH + 1 * MM, nullptr, Kf, nullptr, nullptr, TK, lb_k, M_, D_, D_);
    gemm_tc<2><<<gD, 256, GEMM_SMEM>>>(AH, WH + 2 * MM, bv,      Vf, nullptr, nullptr, TV, lb_v, M_, D_, D_);
    // 6. attention -> ctx fp16 (overwrites AH)
    attn_kernel<<<B_ * NH_ * (S_ / 64), 256>>>(Qf, Kf, Vf, AH);
    // 7. LoRA down for o
    lora_down_kernel<<<M_, 256>>>(AH, la_o, nullptr, TO, nullptr);
    // 8. O projection: X1 = x + ctx@Wo^T + bo + lora_o
    gemm_tc<3><<<gD, 256, GEMM_SMEM>>>(AH, WH + 3 * MM, bo, X1, nullptr, x, TO, lb_o, M_, D_, D_);
    // 9. LN2 -> fp16
    ln_fp16_kernel<<<M_, 256>>>(X1, g_mlp, b_mlp, AH);
    // 10. MLP1: gelu -> fp16
    gemm_tc<1><<<gF, 256, GEMM_SMEM>>>(AH, WH + 4 * MM, b1, nullptr, UH, nullptr, nullptr, nullptr, M_, DFF_, D_);
    // 11. MLP2: out = X1 + U@W2^T + b2
    gemm_tc<4><<<gD, 256, GEMM_SMEM>>>(UH, WH + 8 * MM, b2, out, nullptr, X1, nullptr, nullptr, M_, D_, DFF_);
}